// round 4
// baseline (speedup 1.0000x reference)
#include <cuda_runtime.h>
#include <math.h>
#include <stdint.h>

#define TT   8192
#define EE   1024
#define HH   16
#define DD   64
#define NSEG 8
#define LL   1024

typedef unsigned long long u64;

// Scratch (device globals — no allocation allowed in kernel_launch)
__device__ float g_q [TT * EE];
__device__ float g_k [TT * EE];
__device__ float g_v [TT * EE];
__device__ float g_ao[TT * EE];

// ---------------------------------------------------------------------------
// f32x2 helpers (packed 2-wide fp32 — FFMA2 on sm_103)
// ---------------------------------------------------------------------------
__device__ __forceinline__ void fma2(u64& d, u64 a, u64 b) {
    asm("fma.rn.f32x2 %0, %1, %2, %0;" : "+l"(d) : "l"(a), "l"(b));
}
__device__ __forceinline__ void mul2(u64& d, u64 a) {
    asm("mul.rn.f32x2 %0, %0, %1;" : "+l"(d) : "l"(a));
}
__device__ __forceinline__ u64 pack2(float x, float y) {
    u64 r; asm("mov.b64 %0, {%1,%2};" : "=l"(r) : "f"(x), "f"(y)); return r;
}
__device__ __forceinline__ float lo2(u64 v) { return __uint_as_float((unsigned)v); }
__device__ __forceinline__ float hi2(u64 v) { return __uint_as_float((unsigned)(v >> 32)); }

// ---------------------------------------------------------------------------
// f32x2 GEMM: C[M,N] = A[M,K] @ B[N,K]^T + bias.  M=8192, N=K=1024.
// 128x128x32 tile, 256 threads, 8x8 strided micro-tile, stride-34 smem.
// ---------------------------------------------------------------------------
#define ASTR 34
#define GBK  32

__global__ __launch_bounds__(256, 1)
void gemm_f2(const float* __restrict__ A, const float* __restrict__ B,
             const float* __restrict__ bias, float* __restrict__ C)
{
    extern __shared__ float sm[];
    float* As = sm;                    // [128][ASTR]
    float* Bs = sm + 128 * ASTR;

    const int tid = threadIdx.x;
    const int ty  = tid >> 4;          // 0..15
    const int tx  = tid & 15;          // 0..15
    const int rowBase = blockIdx.y * 128;
    const int colBase = blockIdx.x * 128;

    const int lr = tid >> 1;           // 0..127 loader row
    const int lc = (tid & 1) * 16;     // 0 or 16

    const float* Aptr = A + (size_t)(rowBase + lr) * EE + lc;
    const float* Bptr = B + (size_t)(colBase + lr) * EE + lc;

    u64 acc[8][8];
#pragma unroll
    for (int i = 0; i < 8; i++)
#pragma unroll
        for (int j = 0; j < 8; j++) acc[i][j] = 0ull;

    float4 pa[4], pb[4];
#pragma unroll
    for (int p = 0; p < 4; p++) {
        pa[p] = *(const float4*)(Aptr + 4 * p);
        pb[p] = *(const float4*)(Bptr + 4 * p);
    }

    const int NSLAB = EE / GBK;
    for (int s = 0; s < NSLAB; s++) {
        __syncthreads();
#pragma unroll
        for (int p = 0; p < 4; p++) {
            *(float2*)&As[lr * ASTR + lc + 4 * p]     = make_float2(pa[p].x, pa[p].y);
            *(float2*)&As[lr * ASTR + lc + 4 * p + 2] = make_float2(pa[p].z, pa[p].w);
            *(float2*)&Bs[lr * ASTR + lc + 4 * p]     = make_float2(pb[p].x, pb[p].y);
            *(float2*)&Bs[lr * ASTR + lc + 4 * p + 2] = make_float2(pb[p].z, pb[p].w);
        }
        __syncthreads();

        if (s + 1 < NSLAB) {
            const int k0 = (s + 1) * GBK;
#pragma unroll
            for (int p = 0; p < 4; p++) {
                pa[p] = *(const float4*)(Aptr + k0 + 4 * p);
                pb[p] = *(const float4*)(Bptr + k0 + 4 * p);
            }
        }

#pragma unroll
        for (int kp = 0; kp < GBK / 2; kp++) {
            u64 a2[8], b2[8];
#pragma unroll
            for (int i = 0; i < 8; i++)
                a2[i] = *(const u64*)&As[(ty + 16 * i) * ASTR + 2 * kp];
#pragma unroll
            for (int j = 0; j < 8; j++)
                b2[j] = *(const u64*)&Bs[(tx + 16 * j) * ASTR + 2 * kp];
#pragma unroll
            for (int i = 0; i < 8; i++)
#pragma unroll
                for (int j = 0; j < 8; j++)
                    fma2(acc[i][j], a2[i], b2[j]);
        }
    }

#pragma unroll
    for (int i = 0; i < 8; i++) {
        const size_t row = (size_t)(rowBase + ty + 16 * i);
#pragma unroll
        for (int j = 0; j < 8; j++) {
            const int col = colBase + tx + 16 * j;
            const float bj = bias ? bias[col] : 0.f;
            C[row * EE + col] = lo2(acc[i][j]) + hi2(acc[i][j]) + bj;
        }
    }
}

// ---------------------------------------------------------------------------
// Flash-style block-diagonal attention with f32x2 inner products.
// grid (LL/64, HH, NSEG), 256 threads. Thread (ty,tx): rows ty+16i, cols tx+16j.
// S: pack over d.  PV: pack over c via transposed V tile (Vt[j][c]).
// ---------------------------------------------------------------------------
#define SROW 66

__global__ __launch_bounds__(256, 2)
void attn_kernel(const float* __restrict__ mask)
{
    extern __shared__ float sm[];
    float* Qs = sm;                  // [64][SROW]
    float* Ks = Qs + 64 * SROW;
    float* Vt = Ks + 64 * SROW;      // transposed: Vt[j][c]
    float* Ss = Vt + 64 * SROW;

    const int seg = blockIdx.z;
    const int h   = blockIdx.y;
    const int q0  = blockIdx.x * 64;
    const int tid = threadIdx.x;
    const int ty  = tid >> 4;
    const int tx  = tid & 15;

    const float scaling = 0.125f;

    // Load + pre-scale Q
    for (int i = tid; i < 64 * 16; i += 256) {
        const int r = i >> 4, c4 = (i & 15) * 4;
        float4 qv = *(const float4*)&g_q[(size_t)(seg * LL + q0 + r) * EE + h * DD + c4];
        qv.x *= scaling; qv.y *= scaling; qv.z *= scaling; qv.w *= scaling;
        *(float2*)&Qs[r * SROW + c4]     = make_float2(qv.x, qv.y);
        *(float2*)&Qs[r * SROW + c4 + 2] = make_float2(qv.z, qv.w);
    }

    u64 o2[4][4];
    float mrow[4], lrow[4];
#pragma unroll
    for (int i = 0; i < 4; i++) {
        mrow[i] = -INFINITY; lrow[i] = 0.f;
#pragma unroll
        for (int j = 0; j < 4; j++) o2[i][j] = 0ull;
    }

    // V transpose loader mapping: row c = tid>>2, j group = (tid&3)*16
    const int vc = tid >> 2;
    const int vj = (tid & 3) * 16;

    for (int kt = 0; kt < 16; kt++) {
        const int k0g = kt * 64;
        __syncthreads();   // prev iter's Ks/Vt/Ss reads complete

        // K tile (row-major) + V tile (transposed)
        for (int i = tid; i < 64 * 16; i += 256) {
            const int r = i >> 4, c4 = (i & 15) * 4;
            float4 kv = *(const float4*)&g_k[(size_t)(seg * LL + k0g + r) * EE + h * DD + c4];
            *(float2*)&Ks[r * SROW + c4]     = make_float2(kv.x, kv.y);
            *(float2*)&Ks[r * SROW + c4 + 2] = make_float2(kv.z, kv.w);
        }
        {
            const size_t vsrc = (size_t)(seg * LL + k0g + vc) * EE + h * DD + vj;
#pragma unroll
            for (int p = 0; p < 4; p++) {
                float4 vv = *(const float4*)&g_v[vsrc + 4 * p];
                Vt[(vj + 4 * p + 0) * SROW + vc] = vv.x;
                Vt[(vj + 4 * p + 1) * SROW + vc] = vv.y;
                Vt[(vj + 4 * p + 2) * SROW + vc] = vv.z;
                Vt[(vj + 4 * p + 3) * SROW + vc] = vv.w;
            }
        }
        __syncthreads();

        // S = Q @ K^T  (f32x2 packed over d)
        u64 s2[4][4];
#pragma unroll
        for (int i = 0; i < 4; i++)
#pragma unroll
            for (int j = 0; j < 4; j++) s2[i][j] = 0ull;

#pragma unroll
        for (int dp = 0; dp < 32; dp++) {
            u64 a2[4], b2[4];
#pragma unroll
            for (int i = 0; i < 4; i++)
                a2[i] = *(const u64*)&Qs[(ty + 16 * i) * SROW + 2 * dp];
#pragma unroll
            for (int j = 0; j < 4; j++)
                b2[j] = *(const u64*)&Ks[(tx + 16 * j) * SROW + 2 * dp];
#pragma unroll
            for (int i = 0; i < 4; i++)
#pragma unroll
                for (int j = 0; j < 4; j++)
                    fma2(s2[i][j], a2[i], b2[j]);
        }

        float s[4][4];
#pragma unroll
        for (int i = 0; i < 4; i++) {
            const size_t mr = (size_t)(seg * LL + q0 + ty + 16 * i) * TT + seg * LL + k0g;
#pragma unroll
            for (int j = 0; j < 4; j++)
                s[i][j] = lo2(s2[i][j]) + hi2(s2[i][j]) + mask[mr + tx + 16 * j];
        }

        // online softmax per owned row
#pragma unroll
        for (int i = 0; i < 4; i++) {
            float mt = fmaxf(fmaxf(s[i][0], s[i][1]), fmaxf(s[i][2], s[i][3]));
#pragma unroll
            for (int w = 1; w < 16; w <<= 1)
                mt = fmaxf(mt, __shfl_xor_sync(0xffffffffu, mt, w, 16));
            const float mnew = fmaxf(mrow[i], mt);
            const float alpha = __expf(mrow[i] - mnew);
            mrow[i] = mnew;
            float rs = 0.f;
#pragma unroll
            for (int j = 0; j < 4; j++) {
                const float p = __expf(s[i][j] - mnew);
                s[i][j] = p;
                rs += p;
            }
#pragma unroll
            for (int w = 1; w < 16; w <<= 1)
                rs += __shfl_xor_sync(0xffffffffu, rs, w, 16);
            lrow[i] = lrow[i] * alpha + rs;

            const u64 al2 = pack2(alpha, alpha);
#pragma unroll
            for (int j = 0; j < 4; j++) mul2(o2[i][j], al2);
        }

#pragma unroll
        for (int i = 0; i < 4; i++)
#pragma unroll
            for (int j = 0; j < 4; j++)
                Ss[(ty + 16 * i) * SROW + tx + 16 * j] = s[i][j];
        __syncthreads();

        // O += P @ V  (f32x2 packed over c; Vt is [j][c])
#pragma unroll
        for (int cp = 0; cp < 32; cp++) {
            u64 p2[4], v2[4];
#pragma unroll
            for (int i = 0; i < 4; i++)
                p2[i] = *(const u64*)&Ss[(ty + 16 * i) * SROW + 2 * cp];
#pragma unroll
            for (int j = 0; j < 4; j++)
                v2[j] = *(const u64*)&Vt[(tx + 16 * j) * SROW + 2 * cp];
#pragma unroll
            for (int i = 0; i < 4; i++)
#pragma unroll
                for (int j = 0; j < 4; j++)
                    fma2(o2[i][j], p2[i], v2[j]);
        }
    }

    // normalize + write
#pragma unroll
    for (int i = 0; i < 4; i++) {
        const float inv = 1.f / lrow[i];
        const size_t row = (size_t)(seg * LL + q0 + ty + 16 * i);
#pragma unroll
        for (int j = 0; j < 4; j++)
            g_ao[row * EE + h * DD + tx + 16 * j] = (lo2(o2[i][j]) + hi2(o2[i][j])) * inv;
    }
}

// ---------------------------------------------------------------------------

extern "C" void kernel_launch(void* const* d_in, const int* in_sizes, int n_in,
                              void* d_out, int out_size)
{
    const float* hs   = (const float*)d_in[0];
    const float* mask = (const float*)d_in[2];
    const float* wq   = (const float*)d_in[3];
    const float* bq   = (const float*)d_in[4];
    const float* wk   = (const float*)d_in[5];
    const float* wv   = (const float*)d_in[6];
    const float* bv   = (const float*)d_in[7];
    const float* wo   = (const float*)d_in[8];
    const float* bo   = (const float*)d_in[9];
    float* out = (float*)d_out;

    float *qp, *kp, *vp, *aop;
    cudaGetSymbolAddress((void**)&qp,  g_q);
    cudaGetSymbolAddress((void**)&kp,  g_k);
    cudaGetSymbolAddress((void**)&vp,  g_v);
    cudaGetSymbolAddress((void**)&aop, g_ao);

    const int gsmem = 2 * 128 * ASTR * (int)sizeof(float);   // 34816
    cudaFuncSetAttribute(gemm_f2, cudaFuncAttributeMaxDynamicSharedMemorySize, gsmem);
    const int asmem = 4 * 64 * SROW * (int)sizeof(float);    // 67584
    cudaFuncSetAttribute(attn_kernel, cudaFuncAttributeMaxDynamicSharedMemorySize, asmem);

    const dim3 gg(EE / 128, TT / 128);

    gemm_f2<<<gg, 256, gsmem>>>(hs, wq, bq,      qp);
    gemm_f2<<<gg, 256, gsmem>>>(hs, wk, nullptr, kp);
    gemm_f2<<<gg, 256, gsmem>>>(hs, wv, bv,      vp);

    attn_kernel<<<dim3(LL / 64, HH, NSEG), 256, asmem>>>(mask);

    gemm_f2<<<gg, 256, gsmem>>>(aop, wo, bo, out);
}

// round 5
// speedup vs baseline: 1.8579x; 1.8579x over previous
#include <cuda_runtime.h>
#include <math.h>
#include <stdint.h>

#define TT   8192
#define EE   1024
#define HH   16
#define DD   64
#define NSEG 8
#define LL   1024

// Scratch (device globals — no allocation allowed in kernel_launch)
__device__ float g_q  [TT * EE];
__device__ float g_k  [TT * EE];
__device__ float g_v  [TT * EE];
__device__ float g_ao [TT * EE];
__device__ float g_at [TT * EE];   // tf32-rounded activations
__device__ float g_wt [EE * EE];   // tf32-rounded weight (reused per GEMM)

// ---------------------------------------------------------------------------
// Elementwise round-to-nearest tf32
// ---------------------------------------------------------------------------
__global__ void round_tf32_kernel(const float* __restrict__ in,
                                  float* __restrict__ out, int n4)
{
    int i = blockIdx.x * blockDim.x + threadIdx.x;
    if (i >= n4) return;
    float4 v = ((const float4*)in)[i];
    uint32_t r0, r1, r2, r3;
    asm("cvt.rna.tf32.f32 %0, %1;" : "=r"(r0) : "f"(v.x));
    asm("cvt.rna.tf32.f32 %0, %1;" : "=r"(r1) : "f"(v.y));
    asm("cvt.rna.tf32.f32 %0, %1;" : "=r"(r2) : "f"(v.z));
    asm("cvt.rna.tf32.f32 %0, %1;" : "=r"(r3) : "f"(v.w));
    float4 o;
    o.x = __uint_as_float(r0); o.y = __uint_as_float(r1);
    o.z = __uint_as_float(r2); o.w = __uint_as_float(r3);
    ((float4*)out)[i] = o;
}

// ---------------------------------------------------------------------------
// TF32 mma.sync GEMM: C[M,N] = A[M,K] @ B[N,K]^T + bias.  M=8192, N=K=1024.
// 128x128 tile, BK=16, 4-stage cp.async, 8 warps (2x4), warp tile 64x32.
// ---------------------------------------------------------------------------
#define GSA     20                        // smem row stride (floats)
#define ABYTES  (128 * GSA * 4)           // 10240
#define STAGEB  (2 * ABYTES)              // 20480
#define NSTAGE  4
#define NSLAB   (EE / 16)                 // 64

__device__ __forceinline__ void cp_async16(uint32_t dst, const void* src) {
    asm volatile("cp.async.cg.shared.global [%0], [%1], 16;\n" :: "r"(dst), "l"(src));
}
__device__ __forceinline__ void cp_commit() { asm volatile("cp.async.commit_group;\n"); }
template <int N> __device__ __forceinline__ void cp_wait() {
    asm volatile("cp.async.wait_group %0;\n" :: "n"(N));
}

__global__ __launch_bounds__(256, 2)
void gemm_tc(const float* __restrict__ A, const float* __restrict__ B,
             const float* __restrict__ bias, float* __restrict__ C)
{
    extern __shared__ float sm[];
    const uint32_t smemBase = (uint32_t)__cvta_generic_to_shared(sm);

    const int tid  = threadIdx.x;
    const int warp = tid >> 5;
    const int lane = tid & 31;
    const int rowBase = blockIdx.y * 128;
    const int colBase = blockIdx.x * 128;

    const int mW = (warp >> 2) * 64;      // 4 mi of 16
    const int nW = (warp & 3) * 32;       // 2 njp of 16 (4 nj of 8)

    // loader: thread t -> rows {t>>2, t>>2+64}, float chunk (t&3)*4
    const int lr = tid >> 2;              // 0..63
    const int lc = (tid & 3) * 4;         // 0,4,8,12

    const float* Aptr = A + (size_t)(rowBase + lr) * EE + lc;
    const float* Bptr = B + (size_t)(colBase + lr) * EE + lc;
    const uint32_t sA = smemBase + (uint32_t)((lr * GSA + lc) * 4);
    const uint32_t sB = sA + ABYTES;
    const uint32_t rowOff64 = (uint32_t)(64 * GSA * 4);

    // ldmatrix source offsets (within a stage buffer)
    uint32_t aoff[4], boff[2];
#pragma unroll
    for (int mi = 0; mi < 4; mi++)
        aoff[mi] = (uint32_t)((((mW + mi * 16 + (lane & 15)) * GSA) + ((lane >> 4) << 2)) << 2);
#pragma unroll
    for (int np = 0; np < 2; np++)
        boff[np] = (uint32_t)((((nW + np * 16 + (lane & 7) + ((lane >> 4) << 3)) * GSA)
                               + (((lane >> 3) & 1) << 2)) << 2) + ABYTES;

    float c[4][4][4];
#pragma unroll
    for (int mi = 0; mi < 4; mi++)
#pragma unroll
        for (int nj = 0; nj < 4; nj++)
#pragma unroll
            for (int r = 0; r < 4; r++) c[mi][nj][r] = 0.f;

    // prologue: stages 0..2
#pragma unroll
    for (int st = 0; st < NSTAGE - 1; st++) {
        const uint32_t bb = st * STAGEB;
        const int k0 = st * 16;
        cp_async16(sA + bb,            Aptr + k0);
        cp_async16(sA + bb + rowOff64, Aptr + (size_t)64 * EE + k0);
        cp_async16(sB + bb,            Bptr + k0);
        cp_async16(sB + bb + rowOff64, Bptr + (size_t)64 * EE + k0);
        cp_commit();
    }

    for (int s = 0; s < NSLAB; s++) {
        cp_wait<2>();
        __syncthreads();

        const uint32_t bb = (uint32_t)(s & 3) * STAGEB;
#pragma unroll
        for (int kk = 0; kk < 2; kk++) {
            const uint32_t ko = (uint32_t)(kk * 32);
            uint32_t a[4][4], b[2][4];
#pragma unroll
            for (int mi = 0; mi < 4; mi++)
                asm volatile("ldmatrix.sync.aligned.m8n8.x4.shared.b16 {%0,%1,%2,%3}, [%4];"
                             : "=r"(a[mi][0]), "=r"(a[mi][1]), "=r"(a[mi][2]), "=r"(a[mi][3])
                             : "r"(smemBase + bb + aoff[mi] + ko));
#pragma unroll
            for (int np = 0; np < 2; np++)
                asm volatile("ldmatrix.sync.aligned.m8n8.x4.shared.b16 {%0,%1,%2,%3}, [%4];"
                             : "=r"(b[np][0]), "=r"(b[np][1]), "=r"(b[np][2]), "=r"(b[np][3])
                             : "r"(smemBase + bb + boff[np] + ko));
#pragma unroll
            for (int mi = 0; mi < 4; mi++)
#pragma unroll
                for (int nj = 0; nj < 4; nj++) {
                    const int np = nj >> 1, hb = (nj & 1) << 1;
                    asm volatile(
                        "mma.sync.aligned.m16n8k8.row.col.f32.tf32.tf32.f32 "
                        "{%0,%1,%2,%3}, {%4,%5,%6,%7}, {%8,%9}, {%0,%1,%2,%3};"
                        : "+f"(c[mi][nj][0]), "+f"(c[mi][nj][1]),
                          "+f"(c[mi][nj][2]), "+f"(c[mi][nj][3])
                        : "r"(a[mi][0]), "r"(a[mi][1]), "r"(a[mi][2]), "r"(a[mi][3]),
                          "r"(b[np][hb]), "r"(b[np][hb + 1]));
                }
        }
        __syncthreads();

        // issue stage s+3 (safe: all warps finished reading buffer (s-1)&3)
        const int sn = s + NSTAGE - 1;
        if (sn < NSLAB) {
            const uint32_t nb = (uint32_t)(sn & 3) * STAGEB;
            const int k0 = sn * 16;
            cp_async16(sA + nb,            Aptr + k0);
            cp_async16(sA + nb + rowOff64, Aptr + (size_t)64 * EE + k0);
            cp_async16(sB + nb,            Bptr + k0);
            cp_async16(sB + nb + rowOff64, Bptr + (size_t)64 * EE + k0);
        }
        cp_commit();
    }

    // epilogue
#pragma unroll
    for (int nj = 0; nj < 4; nj++) {
        const int col = colBase + nW + nj * 8 + (lane & 3) * 2;
        const float b0 = bias ? bias[col]     : 0.f;
        const float b1 = bias ? bias[col + 1] : 0.f;
#pragma unroll
        for (int mi = 0; mi < 4; mi++) {
            const int row = rowBase + mW + mi * 16 + (lane >> 2);
            float2 v0 = {c[mi][nj][0] + b0, c[mi][nj][1] + b1};
            float2 v1 = {c[mi][nj][2] + b0, c[mi][nj][3] + b1};
            *(float2*)&C[(size_t)row * EE + col]       = v0;
            *(float2*)&C[(size_t)(row + 8) * EE + col] = v1;
        }
    }
}

// ---------------------------------------------------------------------------
// Flash-style block-diagonal attention (round-1 math, 3 CTAs/SM).
// ---------------------------------------------------------------------------
#define SROW 68

__global__ __launch_bounds__(256, 3)
void attn_kernel(const float* __restrict__ mask)
{
    extern __shared__ float sm[];
    float* Qs = sm;
    float* Ks = Qs + 64 * SROW;
    float* Vs = Ks + 64 * SROW;
    float* Ss = Vs + 64 * SROW;

    const int seg = blockIdx.z;
    const int h   = blockIdx.y;
    const int q0  = blockIdx.x * 64;
    const int tid = threadIdx.x;
    const int ty  = tid >> 4;
    const int tx  = tid & 15;

    const float scaling = 0.125f;

    for (int i = tid; i < 64 * 16; i += 256) {
        const int r = i >> 4, c4 = (i & 15) * 4;
        float4 qv = *(const float4*)&g_q[(size_t)(seg * LL + q0 + r) * EE + h * DD + c4];
        qv.x *= scaling; qv.y *= scaling; qv.z *= scaling; qv.w *= scaling;
        *(float4*)&Qs[r * SROW + c4] = qv;
    }

    float o[4][4];
    float mrow[4], lrow[4];
#pragma unroll
    for (int i = 0; i < 4; i++) {
        mrow[i] = -INFINITY; lrow[i] = 0.f;
#pragma unroll
        for (int j = 0; j < 4; j++) o[i][j] = 0.f;
    }

    for (int kt = 0; kt < 16; kt++) {
        const int k0g = kt * 64;
        __syncthreads();
        for (int i = tid; i < 64 * 16; i += 256) {
            const int r = i >> 4, c4 = (i & 15) * 4;
            const size_t src = (size_t)(seg * LL + k0g + r) * EE + h * DD + c4;
            *(float4*)&Ks[r * SROW + c4] = *(const float4*)&g_k[src];
            *(float4*)&Vs[r * SROW + c4] = *(const float4*)&g_v[src];
        }
        __syncthreads();

        float s[4][4];
#pragma unroll
        for (int i = 0; i < 4; i++)
#pragma unroll
            for (int j = 0; j < 4; j++) s[i][j] = 0.f;

#pragma unroll
        for (int d = 0; d < 64; d += 4) {
            float4 qv[4], kv[4];
#pragma unroll
            for (int i = 0; i < 4; i++) qv[i] = *(const float4*)&Qs[(ty + 16 * i) * SROW + d];
#pragma unroll
            for (int j = 0; j < 4; j++) kv[j] = *(const float4*)&Ks[(tx + 16 * j) * SROW + d];
#pragma unroll
            for (int i = 0; i < 4; i++)
#pragma unroll
                for (int j = 0; j < 4; j++) {
                    s[i][j] = fmaf(qv[i].x, kv[j].x, s[i][j]);
                    s[i][j] = fmaf(qv[i].y, kv[j].y, s[i][j]);
                    s[i][j] = fmaf(qv[i].z, kv[j].z, s[i][j]);
                    s[i][j] = fmaf(qv[i].w, kv[j].w, s[i][j]);
                }
        }

#pragma unroll
        for (int i = 0; i < 4; i++) {
            const size_t mr = (size_t)(seg * LL + q0 + ty + 16 * i) * TT + seg * LL + k0g;
#pragma unroll
            for (int j = 0; j < 4; j++)
                s[i][j] += mask[mr + tx + 16 * j];
        }

        float alpha[4];
#pragma unroll
        for (int i = 0; i < 4; i++) {
            float mt = fmaxf(fmaxf(s[i][0], s[i][1]), fmaxf(s[i][2], s[i][3]));
#pragma unroll
            for (int w = 1; w < 16; w <<= 1)
                mt = fmaxf(mt, __shfl_xor_sync(0xffffffffu, mt, w, 16));
            const float mnew = fmaxf(mrow[i], mt);
            alpha[i] = __expf(mrow[i] - mnew);
            mrow[i]  = mnew;
            float rs = 0.f;
#pragma unroll
            for (int j = 0; j < 4; j++) {
                const float p = __expf(s[i][j] - mnew);
                s[i][j] = p;
                rs += p;
            }
#pragma unroll
            for (int w = 1; w < 16; w <<= 1)
                rs += __shfl_xor_sync(0xffffffffu, rs, w, 16);
            lrow[i] = lrow[i] * alpha[i] + rs;
        }

#pragma unroll
        for (int i = 0; i < 4; i++) {
#pragma unroll
            for (int j = 0; j < 4; j++)
                Ss[(ty + 16 * i) * SROW + tx + 16 * j] = s[i][j];
#pragma unroll
            for (int j = 0; j < 4; j++) o[i][j] *= alpha[i];
        }
        __syncthreads();

#pragma unroll
        for (int cb = 0; cb < 64; cb += 4) {
            float4 p4[4];
#pragma unroll
            for (int i = 0; i < 4; i++)
                p4[i] = *(const float4*)&Ss[(ty + 16 * i) * SROW + cb];
#pragma unroll
            for (int cc = 0; cc < 4; cc++) {
                float vv[4];
#pragma unroll
                for (int j = 0; j < 4; j++)
                    vv[j] = Vs[(cb + cc) * SROW + tx + 16 * j];
#pragma unroll
                for (int i = 0; i < 4; i++) {
                    const float pi = ((const float*)&p4[i])[cc];
#pragma unroll
                    for (int j = 0; j < 4; j++)
                        o[i][j] = fmaf(pi, vv[j], o[i][j]);
                }
            }
        }
    }

#pragma unroll
    for (int i = 0; i < 4; i++) {
        const float inv = 1.f / lrow[i];
        const size_t row = (size_t)(seg * LL + q0 + ty + 16 * i);
#pragma unroll
        for (int j = 0; j < 4; j++)
            g_ao[row * EE + h * DD + tx + 16 * j] = o[i][j] * inv;
    }
}

// ---------------------------------------------------------------------------

extern "C" void kernel_launch(void* const* d_in, const int* in_sizes, int n_in,
                              void* d_out, int out_size)
{
    const float* hs   = (const float*)d_in[0];
    const float* mask = (const float*)d_in[2];
    const float* wq   = (const float*)d_in[3];
    const float* bq   = (const float*)d_in[4];
    const float* wk   = (const float*)d_in[5];
    const float* wv   = (const float*)d_in[6];
    const float* bv   = (const float*)d_in[7];
    const float* wo   = (const float*)d_in[8];
    const float* bo   = (const float*)d_in[9];
    float* out = (float*)d_out;

    float *qp, *kp, *vp, *aop, *atp, *wtp;
    cudaGetSymbolAddress((void**)&qp,  g_q);
    cudaGetSymbolAddress((void**)&kp,  g_k);
    cudaGetSymbolAddress((void**)&vp,  g_v);
    cudaGetSymbolAddress((void**)&aop, g_ao);
    cudaGetSymbolAddress((void**)&atp, g_at);
    cudaGetSymbolAddress((void**)&wtp, g_wt);

    const int gsmem = NSTAGE * STAGEB;                      // 81920
    cudaFuncSetAttribute(gemm_tc, cudaFuncAttributeMaxDynamicSharedMemorySize, gsmem);
    const int asmem = 4 * 64 * SROW * (int)sizeof(float);   // 69632
    cudaFuncSetAttribute(attn_kernel, cudaFuncAttributeMaxDynamicSharedMemorySize, asmem);

    const dim3 gg(EE / 128, TT / 128);
    const int nAct4 = TT * EE / 4;
    const int nW4   = EE * EE / 4;

    round_tf32_kernel<<<nAct4 / 256, 256>>>(hs, atp, nAct4);

    round_tf32_kernel<<<nW4 / 256, 256>>>(wq, wtp, nW4);
    gemm_tc<<<gg, 256, gsmem>>>(atp, wtp, bq, qp);
    round_tf32_kernel<<<nW4 / 256, 256>>>(wk, wtp, nW4);
    gemm_tc<<<gg, 256, gsmem>>>(atp, wtp, nullptr, kp);
    round_tf32_kernel<<<nW4 / 256, 256>>>(wv, wtp, nW4);
    gemm_tc<<<gg, 256, gsmem>>>(atp, wtp, bv, vp);

    attn_kernel<<<dim3(LL / 64, HH, NSEG), 256, asmem>>>(mask);

    round_tf32_kernel<<<nAct4 / 256, 256>>>(aop, atp, nAct4);
    round_tf32_kernel<<<nW4 / 256, 256>>>(wo, wtp, nW4);
    gemm_tc<<<gg, 256, gsmem>>>(atp, wtp, bo, out);
}

// round 6
// speedup vs baseline: 2.4100x; 1.2972x over previous
#include <cuda_runtime.h>
#include <math.h>
#include <stdint.h>

#define TT   8192
#define EE   1024
#define HH   16
#define DD   64
#define NSEG 8
#define LL   1024

// Scratch (device globals — no allocation allowed in kernel_launch)
__device__ float g_q  [TT * EE];
__device__ float g_k  [TT * EE];
__device__ float g_v  [TT * EE];
__device__ float g_ao [TT * EE];
__device__ float g_at [TT * EE];   // tf32-rounded activations
__device__ float g_wt [EE * EE];   // tf32-rounded weight (reused per GEMM)
__device__ float g_vt [EE * TT];   // transposed+rounded V: [e][token]

// ---------------------------------------------------------------------------
// helpers
// ---------------------------------------------------------------------------
__device__ __forceinline__ float rna(float x) {
    uint32_t r; asm("cvt.rna.tf32.f32 %0, %1;" : "=r"(r) : "f"(x));
    return __uint_as_float(r);
}
__device__ __forceinline__ void ldsm4(uint32_t* r, uint32_t addr) {
    asm volatile("ldmatrix.sync.aligned.m8n8.x4.shared.b16 {%0,%1,%2,%3}, [%4];"
                 : "=r"(r[0]), "=r"(r[1]), "=r"(r[2]), "=r"(r[3]) : "r"(addr));
}
__device__ __forceinline__ void mma8(float* c, const uint32_t* a, uint32_t b0, uint32_t b1) {
    asm volatile("mma.sync.aligned.m16n8k8.row.col.f32.tf32.tf32.f32 "
                 "{%0,%1,%2,%3}, {%4,%5,%6,%7}, {%8,%9}, {%0,%1,%2,%3};"
                 : "+f"(c[0]), "+f"(c[1]), "+f"(c[2]), "+f"(c[3])
                 : "r"(a[0]), "r"(a[1]), "r"(a[2]), "r"(a[3]), "r"(b0), "r"(b1));
}
__device__ __forceinline__ void cp_async16(uint32_t dst, const void* src) {
    asm volatile("cp.async.cg.shared.global [%0], [%1], 16;\n" :: "r"(dst), "l"(src));
}
__device__ __forceinline__ void cp_commit() { asm volatile("cp.async.commit_group;\n"); }
template <int N> __device__ __forceinline__ void cp_wait() {
    asm volatile("cp.async.wait_group %0;\n" :: "n"(N));
}

// ---------------------------------------------------------------------------
// Elementwise round-to-nearest tf32
// ---------------------------------------------------------------------------
__global__ void round_tf32_kernel(const float* __restrict__ in,
                                  float* __restrict__ out, int n4)
{
    int i = blockIdx.x * blockDim.x + threadIdx.x;
    if (i >= n4) return;
    float4 v = ((const float4*)in)[i];
    float4 o = {rna(v.x), rna(v.y), rna(v.z), rna(v.w)};
    ((float4*)out)[i] = o;
}

// ---------------------------------------------------------------------------
// V transpose + round: g_v[token][e] -> g_vt[e][token]
// ---------------------------------------------------------------------------
__global__ void vt_round_kernel(const float* __restrict__ v, float* __restrict__ vt)
{
    __shared__ float t[32][33];
    const int bx = blockIdx.x * 32;   // token base
    const int by = blockIdx.y * 32;   // e base
    const int x = threadIdx.x, y = threadIdx.y;
#pragma unroll
    for (int i = 0; i < 32; i += 8)
        t[y + i][x] = rna(v[(size_t)(bx + y + i) * EE + by + x]);
    __syncthreads();
#pragma unroll
    for (int i = 0; i < 32; i += 8)
        vt[(size_t)(by + y + i) * TT + bx + x] = t[x][y + i];
}

// ---------------------------------------------------------------------------
// TF32 mma.sync GEMM (round-5 validated): C = A @ B^T + bias, opt. tf32-round C.
// ---------------------------------------------------------------------------
#define GSA     20
#define ABYTES  (128 * GSA * 4)
#define STAGEB  (2 * ABYTES)
#define NSTAGE  4
#define NSLAB   (EE / 16)

__global__ __launch_bounds__(256, 2)
void gemm_tc(const float* __restrict__ A, const float* __restrict__ B,
             const float* __restrict__ bias, float* __restrict__ C, int roundC)
{
    extern __shared__ float sm[];
    const uint32_t smemBase = (uint32_t)__cvta_generic_to_shared(sm);

    const int tid  = threadIdx.x;
    const int warp = tid >> 5;
    const int lane = tid & 31;
    const int rowBase = blockIdx.y * 128;
    const int colBase = blockIdx.x * 128;

    const int mW = (warp >> 2) * 64;
    const int nW = (warp & 3) * 32;

    const int lr = tid >> 2;
    const int lc = (tid & 3) * 4;

    const float* Aptr = A + (size_t)(rowBase + lr) * EE + lc;
    const float* Bptr = B + (size_t)(colBase + lr) * EE + lc;
    const uint32_t sA = smemBase + (uint32_t)((lr * GSA + lc) * 4);
    const uint32_t sB = sA + ABYTES;
    const uint32_t rowOff64 = (uint32_t)(64 * GSA * 4);

    uint32_t aoff[4], boff[2];
#pragma unroll
    for (int mi = 0; mi < 4; mi++)
        aoff[mi] = (uint32_t)((((mW + mi * 16 + (lane & 15)) * GSA) + ((lane >> 4) << 2)) << 2);
#pragma unroll
    for (int np = 0; np < 2; np++)
        boff[np] = (uint32_t)((((nW + np * 16 + (lane & 7) + ((lane >> 4) << 3)) * GSA)
                               + (((lane >> 3) & 1) << 2)) << 2) + ABYTES;

    float c[4][4][4];
#pragma unroll
    for (int mi = 0; mi < 4; mi++)
#pragma unroll
        for (int nj = 0; nj < 4; nj++)
#pragma unroll
            for (int r = 0; r < 4; r++) c[mi][nj][r] = 0.f;

#pragma unroll
    for (int st = 0; st < NSTAGE - 1; st++) {
        const uint32_t bb = st * STAGEB;
        const int k0 = st * 16;
        cp_async16(sA + bb,            Aptr + k0);
        cp_async16(sA + bb + rowOff64, Aptr + (size_t)64 * EE + k0);
        cp_async16(sB + bb,            Bptr + k0);
        cp_async16(sB + bb + rowOff64, Bptr + (size_t)64 * EE + k0);
        cp_commit();
    }

    for (int s = 0; s < NSLAB; s++) {
        cp_wait<2>();
        __syncthreads();

        const uint32_t bb = (uint32_t)(s & 3) * STAGEB;
#pragma unroll
        for (int kk = 0; kk < 2; kk++) {
            const uint32_t ko = (uint32_t)(kk * 32);
            uint32_t a[4][4], b[2][4];
#pragma unroll
            for (int mi = 0; mi < 4; mi++)
                ldsm4(a[mi], smemBase + bb + aoff[mi] + ko);
#pragma unroll
            for (int np = 0; np < 2; np++)
                ldsm4(b[np], smemBase + bb + boff[np] + ko);
#pragma unroll
            for (int mi = 0; mi < 4; mi++)
#pragma unroll
                for (int nj = 0; nj < 4; nj++) {
                    const int np = nj >> 1, hb = (nj & 1) << 1;
                    mma8(c[mi][nj], a[mi], b[np][hb], b[np][hb + 1]);
                }
        }
        __syncthreads();

        const int sn = s + NSTAGE - 1;
        if (sn < NSLAB) {
            const uint32_t nb = (uint32_t)(sn & 3) * STAGEB;
            const int k0 = sn * 16;
            cp_async16(sA + nb,            Aptr + k0);
            cp_async16(sA + nb + rowOff64, Aptr + (size_t)64 * EE + k0);
            cp_async16(sB + nb,            Bptr + k0);
            cp_async16(sB + nb + rowOff64, Bptr + (size_t)64 * EE + k0);
        }
        cp_commit();
    }

#pragma unroll
    for (int nj = 0; nj < 4; nj++) {
        const int col = colBase + nW + nj * 8 + (lane & 3) * 2;
        const float b0 = bias ? bias[col]     : 0.f;
        const float b1 = bias ? bias[col + 1] : 0.f;
#pragma unroll
        for (int mi = 0; mi < 4; mi++) {
            const int row = rowBase + mW + mi * 16 + (lane >> 2);
            float2 v0 = {c[mi][nj][0] + b0, c[mi][nj][1] + b1};
            float2 v1 = {c[mi][nj][2] + b0, c[mi][nj][3] + b1};
            if (roundC) {
                v0.x = rna(v0.x); v0.y = rna(v0.y);
                v1.x = rna(v1.x); v1.y = rna(v1.y);
            }
            *(float2*)&C[(size_t)row * EE + col]       = v0;
            *(float2*)&C[(size_t)(row + 8) * EE + col] = v1;
        }
    }
}

// ---------------------------------------------------------------------------
// Tensor-core flash attention.
// grid (LL/64, HH, NSEG), 128 threads (4 warps). Warp w: q rows [w*16, w*16+16),
// full 64-key width. Ktile = 64 keys, 16 iterations.
// S = Q@K^T via mma (A=Qs, B=Ks); softmax in registers (warp-local rows);
// P -> smem (warp-private rows) -> ldmatrix A; O += P@V via mma (B=Vt tile).
// ---------------------------------------------------------------------------
#define AS 68                       // tile row stride (floats)
#define TILE_B (64 * AS * 4)        // 17408 bytes per tile

__global__ __launch_bounds__(128, 3)
void attn_tc(const float* __restrict__ mask)
{
    extern __shared__ float sm[];
    float* Qs = sm;                 // [64][AS]
    float* Ks = Qs + 64 * AS;
    float* Vt = Ks + 64 * AS;       // [d=64][keys]
    float* Ss = Vt + 64 * AS;       // [q=64][keys]
    const uint32_t smemBase = (uint32_t)__cvta_generic_to_shared(sm);

    const int seg = blockIdx.z;
    const int h   = blockIdx.y;
    const int q0  = blockIdx.x * 64;
    const int tid = threadIdx.x;
    const int warp = tid >> 5;
    const int lane = tid & 31;
    const int r0 = lane >> 2;       // accumulator row within 8
    const int cb = (lane & 3) * 2;  // accumulator col pair base

    // Q load + 0.125 scale (g_q already tf32-rounded; *2^-3 exact)
    for (int i = tid; i < 64 * 16; i += 128) {
        const int r = i >> 4, c4 = (i & 15) * 4;
        float4 qv = *(const float4*)&g_q[(size_t)(seg * LL + q0 + r) * EE + h * DD + c4];
        qv.x *= 0.125f; qv.y *= 0.125f; qv.z *= 0.125f; qv.w *= 0.125f;
        *(float4*)&Qs[r * AS + c4] = qv;
    }

    // fragment smem byte offsets
    const uint32_t qoff = smemBase + (uint32_t)((((warp * 16 + (lane & 15)) * AS)
                                                 + ((lane >> 4) << 2)) << 2);
    const uint32_t poff = qoff + 3u * TILE_B;   // Ss has same row pattern
    uint32_t koff[4], voff[4];
#pragma unroll
    for (int np = 0; np < 4; np++) {
        const uint32_t bo = (uint32_t)((((np * 16 + (lane & 7) + ((lane >> 4) << 3)) * AS)
                                        + (((lane >> 3) & 1) << 2)) << 2);
        koff[np] = smemBase + bo + 1u * TILE_B;
        voff[np] = smemBase + bo + 2u * TILE_B;
    }

    float o[8][4];
#pragma unroll
    for (int nj = 0; nj < 8; nj++)
#pragma unroll
        for (int r = 0; r < 4; r++) o[nj][r] = 0.f;
    float mrow[2] = {-INFINITY, -INFINITY};
    float lrow[2] = {0.f, 0.f};

    for (int kt = 0; kt < 16; kt++) {
        const int k0 = kt * 64;
        __syncthreads();   // prev ktile consumers done (also orders Qs writes at kt=0)

        // load K tile [64 keys][64 d] and Vt tile [64 d][64 keys]
        {
            const int r  = tid >> 1;
            const int cc = (tid & 1) * 32;
            const float* ks = &g_k[(size_t)(seg * LL + k0 + r) * EE + h * DD + cc];
            const float* vs = &g_vt[(size_t)(h * DD + r) * TT + seg * LL + k0 + cc];
            float* kd = &Ks[r * AS + cc];
            float* vd = &Vt[r * AS + cc];
#pragma unroll
            for (int p = 0; p < 8; p++) *(float4*)(kd + 4 * p) = *(const float4*)(ks + 4 * p);
#pragma unroll
            for (int p = 0; p < 8; p++) *(float4*)(vd + 4 * p) = *(const float4*)(vs + 4 * p);
        }
        __syncthreads();

        // ---- S = Q @ K^T ----
        float s[8][4];
#pragma unroll
        for (int nj = 0; nj < 8; nj++)
#pragma unroll
            for (int r = 0; r < 4; r++) s[nj][r] = 0.f;

#pragma unroll
        for (int kd = 0; kd < 8; kd++) {
            const uint32_t ko = (uint32_t)(kd * 32);
            uint32_t a[4], b[4][4];
            ldsm4(a, qoff + ko);
#pragma unroll
            for (int np = 0; np < 4; np++) ldsm4(b[np], koff[np] + ko);
#pragma unroll
            for (int nj = 0; nj < 8; nj++) {
                const int np = nj >> 1, hb = (nj & 1) << 1;
                mma8(s[nj], a, b[np][hb], b[np][hb + 1]);
            }
        }

        // ---- mask add ----
        {
            const size_t mbase = (size_t)(seg * LL + q0 + warp * 16 + r0) * TT
                               + (size_t)(seg * LL + k0) + cb;
#pragma unroll
            for (int nj = 0; nj < 8; nj++) {
                float2 m0 = *(const float2*)&mask[mbase + nj * 8];
                float2 m1 = *(const float2*)&mask[mbase + nj * 8 + (size_t)8 * TT];
                s[nj][0] += m0.x; s[nj][1] += m0.y;
                s[nj][2] += m1.x; s[nj][3] += m1.y;
            }
        }

        // ---- online softmax (rows r0 and r0+8, warp-local) ----
        float mx0 = s[0][0], mx1 = s[0][2];
#pragma unroll
        for (int nj = 0; nj < 8; nj++) {
            mx0 = fmaxf(mx0, fmaxf(s[nj][0], s[nj][1]));
            mx1 = fmaxf(mx1, fmaxf(s[nj][2], s[nj][3]));
        }
        mx0 = fmaxf(mx0, __shfl_xor_sync(0xffffffffu, mx0, 1));
        mx0 = fmaxf(mx0, __shfl_xor_sync(0xffffffffu, mx0, 2));
        mx1 = fmaxf(mx1, __shfl_xor_sync(0xffffffffu, mx1, 1));
        mx1 = fmaxf(mx1, __shfl_xor_sync(0xffffffffu, mx1, 2));

        const float mn0 = fmaxf(mrow[0], mx0);
        const float mn1 = fmaxf(mrow[1], mx1);
        const float al0 = __expf(mrow[0] - mn0);
        const float al1 = __expf(mrow[1] - mn1);
        mrow[0] = mn0; mrow[1] = mn1;

        float sum0 = 0.f, sum1 = 0.f;
#pragma unroll
        for (int nj = 0; nj < 8; nj++) {
            s[nj][0] = __expf(s[nj][0] - mn0); sum0 += s[nj][0];
            s[nj][1] = __expf(s[nj][1] - mn0); sum0 += s[nj][1];
            s[nj][2] = __expf(s[nj][2] - mn1); sum1 += s[nj][2];
            s[nj][3] = __expf(s[nj][3] - mn1); sum1 += s[nj][3];
        }
        sum0 += __shfl_xor_sync(0xffffffffu, sum0, 1);
        sum0 += __shfl_xor_sync(0xffffffffu, sum0, 2);
        sum1 += __shfl_xor_sync(0xffffffffu, sum1, 1);
        sum1 += __shfl_xor_sync(0xffffffffu, sum1, 2);
        lrow[0] = lrow[0] * al0 + sum0;
        lrow[1] = lrow[1] * al1 + sum1;

#pragma unroll
        for (int nj = 0; nj < 8; nj++) {
            o[nj][0] *= al0; o[nj][1] *= al0;
            o[nj][2] *= al1; o[nj][3] *= al1;
        }

        // ---- P -> smem (tf32-rounded), warp-private rows ----
        {
            float* p0 = &Ss[(warp * 16 + r0) * AS + cb];
            float* p1 = &Ss[(warp * 16 + r0 + 8) * AS + cb];
#pragma unroll
            for (int nj = 0; nj < 8; nj++) {
                *(float2*)(p0 + nj * 8) = make_float2(rna(s[nj][0]), rna(s[nj][1]));
                *(float2*)(p1 + nj * 8) = make_float2(rna(s[nj][2]), rna(s[nj][3]));
            }
        }
        __syncwarp();

        // ---- O += P @ V ----
#pragma unroll
        for (int kc = 0; kc < 8; kc++) {
            const uint32_t ko = (uint32_t)(kc * 32);
            uint32_t a[4], b[4][4];
            ldsm4(a, poff + ko);
#pragma unroll
            for (int np = 0; np < 4; np++) ldsm4(b[np], voff[np] + ko);
#pragma unroll
            for (int nj = 0; nj < 8; nj++) {
                const int np = nj >> 1, hb = (nj & 1) << 1;
                mma8(o[nj], a, b[np][hb], b[np][hb + 1]);
            }
        }
    }

    // ---- normalize + write ----
    {
        const float inv0 = 1.f / lrow[0];
        const float inv1 = 1.f / lrow[1];
        const size_t row0 = (size_t)(seg * LL + q0 + warp * 16 + r0);
#pragma unroll
        for (int nj = 0; nj < 8; nj++) {
            const int col = h * DD + nj * 8 + cb;
            *(float2*)&g_ao[row0 * EE + col] =
                make_float2(o[nj][0] * inv0, o[nj][1] * inv0);
            *(float2*)&g_ao[(row0 + 8) * EE + col] =
                make_float2(o[nj][2] * inv1, o[nj][3] * inv1);
        }
    }
}

// ---------------------------------------------------------------------------

extern "C" void kernel_launch(void* const* d_in, const int* in_sizes, int n_in,
                              void* d_out, int out_size)
{
    const float* hs   = (const float*)d_in[0];
    const float* mask = (const float*)d_in[2];
    const float* wq   = (const float*)d_in[3];
    const float* bq   = (const float*)d_in[4];
    const float* wk   = (const float*)d_in[5];
    const float* wv   = (const float*)d_in[6];
    const float* bv   = (const float*)d_in[7];
    const float* wo   = (const float*)d_in[8];
    const float* bo   = (const float*)d_in[9];
    float* out = (float*)d_out;

    float *qp, *kp, *vp, *aop, *atp, *wtp, *vtp;
    cudaGetSymbolAddress((void**)&qp,  g_q);
    cudaGetSymbolAddress((void**)&kp,  g_k);
    cudaGetSymbolAddress((void**)&vp,  g_v);
    cudaGetSymbolAddress((void**)&aop, g_ao);
    cudaGetSymbolAddress((void**)&atp, g_at);
    cudaGetSymbolAddress((void**)&wtp, g_wt);
    cudaGetSymbolAddress((void**)&vtp, g_vt);

    const int gsmem = NSTAGE * STAGEB;            // 81920
    cudaFuncSetAttribute(gemm_tc, cudaFuncAttributeMaxDynamicSharedMemorySize, gsmem);
    const int asmem = 4 * TILE_B;                 // 69632
    cudaFuncSetAttribute(attn_tc, cudaFuncAttributeMaxDynamicSharedMemorySize, asmem);

    const dim3 gg(EE / 128, TT / 128);
    const int nAct4 = TT * EE / 4;
    const int nW4   = EE * EE / 4;

    round_tf32_kernel<<<nAct4 / 256, 256>>>(hs, atp, nAct4);

    round_tf32_kernel<<<nW4 / 256, 256>>>(wq, wtp, nW4);
    gemm_tc<<<gg, 256, gsmem>>>(atp, wtp, bq, qp, 1);       // Q rounded
    round_tf32_kernel<<<nW4 / 256, 256>>>(wk, wtp, nW4);
    gemm_tc<<<gg, 256, gsmem>>>(atp, wtp, nullptr, kp, 1);  // K rounded
    round_tf32_kernel<<<nW4 / 256, 256>>>(wv, wtp, nW4);
    gemm_tc<<<gg, 256, gsmem>>>(atp, wtp, bv, vp, 0);       // V fp32

    vt_round_kernel<<<dim3(TT / 32, EE / 32), dim3(32, 8)>>>(vp, vtp);

    attn_tc<<<dim3(LL / 64, HH, NSEG), 128, asmem>>>(mask);

    round_tf32_kernel<<<nAct4 / 256, 256>>>(aop, atp, nAct4);
    round_tf32_kernel<<<nW4 / 256, 256>>>(wo, wtp, nW4);
    gemm_tc<<<gg, 256, gsmem>>>(atp, wtp, bo, out, 0);
}

// round 7
// speedup vs baseline: 4.6541x; 1.9312x over previous
#include <cuda_runtime.h>
#include <cuda_fp16.h>
#include <math.h>
#include <stdint.h>

#define TT   8192
#define EE   1024
#define HH   16
#define DD   64
#define NSEG 8
#define LL   1024

// Scratch (device globals — no allocation allowed in kernel_launch)
__device__ __half g_hh [TT * EE];       // hs in half
__device__ __half g_wh [4 * EE * EE];   // 4 weights in half
__device__ __half g_qh [TT * EE];       // Q projection (half)
__device__ __half g_kh [TT * EE];       // K projection (half)
__device__ __half g_vth[EE * TT];       // V projection, transposed [e][token]
__device__ __half g_oh [TT * EE];       // attention output (half)

// ---------------------------------------------------------------------------
// helpers
// ---------------------------------------------------------------------------
__device__ __forceinline__ void ldsm4(uint32_t* r, uint32_t addr) {
    asm volatile("ldmatrix.sync.aligned.m8n8.x4.shared.b16 {%0,%1,%2,%3}, [%4];"
                 : "=r"(r[0]), "=r"(r[1]), "=r"(r[2]), "=r"(r[3]) : "r"(addr));
}
__device__ __forceinline__ void mma16(float* c, const uint32_t* a, uint32_t b0, uint32_t b1) {
    asm volatile("mma.sync.aligned.m16n8k16.row.col.f32.f16.f16.f32 "
                 "{%0,%1,%2,%3}, {%4,%5,%6,%7}, {%8,%9}, {%0,%1,%2,%3};"
                 : "+f"(c[0]), "+f"(c[1]), "+f"(c[2]), "+f"(c[3])
                 : "r"(a[0]), "r"(a[1]), "r"(a[2]), "r"(a[3]), "r"(b0), "r"(b1));
}
__device__ __forceinline__ void cp_async16(uint32_t dst, const void* src) {
    asm volatile("cp.async.cg.shared.global [%0], [%1], 16;\n" :: "r"(dst), "l"(src));
}
__device__ __forceinline__ void cp_commit() { asm volatile("cp.async.commit_group;\n"); }
template <int N> __device__ __forceinline__ void cp_wait() {
    asm volatile("cp.async.wait_group %0;\n" :: "n"(N));
}

// ---------------------------------------------------------------------------
// float -> half conversion
// ---------------------------------------------------------------------------
__global__ void f2h_kernel(const float* __restrict__ in, __half* __restrict__ out, int n4)
{
    int i = blockIdx.x * blockDim.x + threadIdx.x;
    if (i >= n4) return;
    float4 v = ((const float4*)in)[i];
    __half2* o = (__half2*)out;
    o[2 * i]     = __floats2half2_rn(v.x, v.y);
    o[2 * i + 1] = __floats2half2_rn(v.z, v.w);
}

// ---------------------------------------------------------------------------
// FP16 mma.sync GEMM: C[M,N] = A[M,K] @ B[N,K]^T (+bias).  M=8192, N=K=1024.
// 128x128 tile, BK=32 halfs, 4-stage cp.async, 8 warps (2x4), warp 64x32.
// mode 0: half C row-major (+bias).  mode 1: half C transposed (vt[col][row]).
// mode 2: float C (+bias).
// ---------------------------------------------------------------------------
#define GH      40                        // smem row stride (halfs)
#define ABY     (128 * GH * 2)            // 10240 bytes per operand tile
#define STGB    (2 * ABY)                 // 20480
#define NSTAGE  4
#define NSLAB   (EE / 32)                 // 32

__global__ __launch_bounds__(256, 2)
void gemm_h(const __half* __restrict__ A, const __half* __restrict__ B,
            const float* __restrict__ bias, __half* __restrict__ Ch,
            float* __restrict__ Cf, int mode)
{
    extern __shared__ char smc[];
    const uint32_t smemBase = (uint32_t)__cvta_generic_to_shared(smc);

    const int tid  = threadIdx.x;
    const int warp = tid >> 5;
    const int lane = tid & 31;
    const int rowBase = blockIdx.y * 128;
    const int colBase = blockIdx.x * 128;

    const int mW = (warp >> 2) * 64;
    const int nW = (warp & 3) * 32;

    // loader: lr = tid>>1 (0..127), chunks at halfs lc and lc+16
    const int lr = tid >> 1;
    const int lc = (tid & 1) * 8;

    const __half* Aptr = A + (size_t)(rowBase + lr) * EE + lc;
    const __half* Bptr = B + (size_t)(colBase + lr) * EE + lc;
    const uint32_t sA = smemBase + (uint32_t)((lr * GH + lc) * 2);
    const uint32_t sB = sA + ABY;

    uint32_t aoff[4], boff[2];
#pragma unroll
    for (int mi = 0; mi < 4; mi++)
        aoff[mi] = (uint32_t)(((mW + mi * 16 + (lane & 15)) * GH + ((lane >> 4) << 3)) << 1);
#pragma unroll
    for (int np = 0; np < 2; np++)
        boff[np] = (uint32_t)(((nW + np * 16 + (lane & 7) + ((lane >> 4) << 3)) * GH
                               + (((lane >> 3) & 1) << 3)) << 1) + ABY;

    float c[4][4][4];
#pragma unroll
    for (int mi = 0; mi < 4; mi++)
#pragma unroll
        for (int nj = 0; nj < 4; nj++)
#pragma unroll
            for (int r = 0; r < 4; r++) c[mi][nj][r] = 0.f;

#pragma unroll
    for (int st = 0; st < NSTAGE - 1; st++) {
        const uint32_t bb = st * STGB;
        const int k0 = st * 32;
        cp_async16(sA + bb,      Aptr + k0);
        cp_async16(sA + bb + 32, Aptr + k0 + 16);
        cp_async16(sB + bb,      Bptr + k0);
        cp_async16(sB + bb + 32, Bptr + k0 + 16);
        cp_commit();
    }

    for (int s = 0; s < NSLAB; s++) {
        cp_wait<2>();
        __syncthreads();

        const uint32_t bb = (uint32_t)(s & 3) * STGB;
#pragma unroll
        for (int kk = 0; kk < 2; kk++) {
            const uint32_t ko = (uint32_t)(kk * 32);   // 16 halfs
            uint32_t a[4][4], b[2][4];
#pragma unroll
            for (int mi = 0; mi < 4; mi++)
                ldsm4(a[mi], smemBase + bb + aoff[mi] + ko);
#pragma unroll
            for (int np = 0; np < 2; np++)
                ldsm4(b[np], smemBase + bb + boff[np] + ko);
#pragma unroll
            for (int mi = 0; mi < 4; mi++)
#pragma unroll
                for (int nj = 0; nj < 4; nj++) {
                    const int np = nj >> 1, hb = (nj & 1) << 1;
                    mma16(c[mi][nj], a[mi], b[np][hb], b[np][hb + 1]);
                }
        }
        __syncthreads();

        const int sn = s + NSTAGE - 1;
        if (sn < NSLAB) {
            const uint32_t nb = (uint32_t)(sn & 3) * STGB;
            const int k0 = sn * 32;
            cp_async16(sA + nb,      Aptr + k0);
            cp_async16(sA + nb + 32, Aptr + k0 + 16);
            cp_async16(sB + nb,      Bptr + k0);
            cp_async16(sB + nb + 32, Bptr + k0 + 16);
        }
        cp_commit();
    }

    // epilogue
#pragma unroll
    for (int nj = 0; nj < 4; nj++) {
        const int col = colBase + nW + nj * 8 + (lane & 3) * 2;
        const float b0 = bias ? bias[col]     : 0.f;
        const float b1 = bias ? bias[col + 1] : 0.f;
#pragma unroll
        for (int mi = 0; mi < 4; mi++) {
            const int row = rowBase + mW + mi * 16 + (lane >> 2);
            const float v00 = c[mi][nj][0] + b0, v01 = c[mi][nj][1] + b1;
            const float v10 = c[mi][nj][2] + b0, v11 = c[mi][nj][3] + b1;
            if (mode == 0) {
                *(__half2*)&Ch[(size_t)row * EE + col]       = __floats2half2_rn(v00, v01);
                *(__half2*)&Ch[(size_t)(row + 8) * EE + col] = __floats2half2_rn(v10, v11);
            } else if (mode == 1) {
                // transposed: vt[col][token=row]
                Ch[(size_t)col * TT + row]           = __float2half_rn(v00);
                Ch[(size_t)(col + 1) * TT + row]     = __float2half_rn(v01);
                Ch[(size_t)col * TT + row + 8]       = __float2half_rn(v10);
                Ch[(size_t)(col + 1) * TT + row + 8] = __float2half_rn(v11);
            } else {
                *(float2*)&Cf[(size_t)row * EE + col]       = make_float2(v00, v01);
                *(float2*)&Cf[(size_t)(row + 8) * EE + col] = make_float2(v10, v11);
            }
        }
    }
}

// ---------------------------------------------------------------------------
// FP16 tensor-core flash attention.
// grid (LL/64, HH, NSEG), 128 threads (4 warps). Warp w: q rows [w*16, w*16+16),
// full 64-key width. Ktile = 64 keys, 16 iterations.
// ---------------------------------------------------------------------------
#define AS     72                        // tile row stride (halfs)
#define TILEH  (64 * AS * 2)             // 9216 bytes

__global__ __launch_bounds__(128, 4)
void attn_h(const float* __restrict__ mask)
{
    extern __shared__ char smc[];
    __half* Qs = (__half*)smc;           // [64][AS]
    __half* Ks = Qs + 64 * AS;
    __half* Vt = Ks + 64 * AS;           // [d=64][keys=64]
    __half* Ss = Vt + 64 * AS;           // [q=64][keys=64]
    const uint32_t smemBase = (uint32_t)__cvta_generic_to_shared(smc);

    const int seg = blockIdx.z;
    const int h   = blockIdx.y;
    const int q0  = blockIdx.x * 64;
    const int tid = threadIdx.x;
    const int warp = tid >> 5;
    const int lane = tid & 31;
    const int r0 = lane >> 2;
    const int cb = (lane & 3) * 2;

    // Q tile load (half, no scale — scale applied to S)
    for (int i = tid; i < 64 * 8; i += 128) {
        const int r = i >> 3, c8 = (i & 7) * 8;
        *(uint4*)&Qs[r * AS + c8] =
            *(const uint4*)&g_qh[(size_t)(seg * LL + q0 + r) * EE + h * DD + c8];
    }

    const uint32_t qoff = smemBase + (uint32_t)(((warp * 16 + (lane & 15)) * AS
                                                 + ((lane >> 4) << 3)) << 1);
    const uint32_t poff = qoff + 3u * TILEH;
    uint32_t koff[4], voff[4];
#pragma unroll
    for (int np = 0; np < 4; np++) {
        const uint32_t bo = (uint32_t)(((np * 16 + (lane & 7) + ((lane >> 4) << 3)) * AS
                                        + (((lane >> 3) & 1) << 3)) << 1);
        koff[np] = smemBase + bo + 1u * TILEH;
        voff[np] = smemBase + bo + 2u * TILEH;
    }

    float o[8][4];
#pragma unroll
    for (int nj = 0; nj < 8; nj++)
#pragma unroll
        for (int r = 0; r < 4; r++) o[nj][r] = 0.f;
    float mrow[2] = {-INFINITY, -INFINITY};
    float lrow[2] = {0.f, 0.f};

    for (int kt = 0; kt < 16; kt++) {
        const int k0 = kt * 64;
        __syncthreads();

        // K tile [key][d] + Vt tile [d][key]
        {
            const int r  = tid >> 1;
            const int cc = (tid & 1) * 32;            // halfs
            const __half* ks = &g_kh[(size_t)(seg * LL + k0 + r) * EE + h * DD + cc];
            const __half* vs = &g_vth[(size_t)(h * DD + r) * TT + seg * LL + k0 + cc];
            __half* kd = &Ks[r * AS + cc];
            __half* vd = &Vt[r * AS + cc];
#pragma unroll
            for (int p = 0; p < 4; p++) *(uint4*)(kd + 8 * p) = *(const uint4*)(ks + 8 * p);
#pragma unroll
            for (int p = 0; p < 4; p++) *(uint4*)(vd + 8 * p) = *(const uint4*)(vs + 8 * p);
        }
        __syncthreads();

        // ---- S = Q @ K^T ----
        float s[8][4];
#pragma unroll
        for (int nj = 0; nj < 8; nj++)
#pragma unroll
            for (int r = 0; r < 4; r++) s[nj][r] = 0.f;

#pragma unroll
        for (int kd = 0; kd < 4; kd++) {
            const uint32_t ko = (uint32_t)(kd * 32);  // 16 halfs
            uint32_t a[4], b[4][4];
            ldsm4(a, qoff + ko);
#pragma unroll
            for (int np = 0; np < 4; np++) ldsm4(b[np], koff[np] + ko);
#pragma unroll
            for (int nj = 0; nj < 8; nj++) {
                const int np = nj >> 1, hb = (nj & 1) << 1;
                mma16(s[nj], a, b[np][hb], b[np][hb + 1]);
            }
        }

        // ---- scale + mask ----
        {
            const size_t mbase = (size_t)(seg * LL + q0 + warp * 16 + r0) * TT
                               + (size_t)(seg * LL + k0) + cb;
#pragma unroll
            for (int nj = 0; nj < 8; nj++) {
                float2 m0 = *(const float2*)&mask[mbase + nj * 8];
                float2 m1 = *(const float2*)&mask[mbase + nj * 8 + (size_t)8 * TT];
                s[nj][0] = s[nj][0] * 0.125f + m0.x;
                s[nj][1] = s[nj][1] * 0.125f + m0.y;
                s[nj][2] = s[nj][2] * 0.125f + m1.x;
                s[nj][3] = s[nj][3] * 0.125f + m1.y;
            }
        }

        // ---- online softmax (rows r0, r0+8; warp-local 4-lane groups) ----
        float mx0 = s[0][0], mx1 = s[0][2];
#pragma unroll
        for (int nj = 0; nj < 8; nj++) {
            mx0 = fmaxf(mx0, fmaxf(s[nj][0], s[nj][1]));
            mx1 = fmaxf(mx1, fmaxf(s[nj][2], s[nj][3]));
        }
        mx0 = fmaxf(mx0, __shfl_xor_sync(0xffffffffu, mx0, 1));
        mx0 = fmaxf(mx0, __shfl_xor_sync(0xffffffffu, mx0, 2));
        mx1 = fmaxf(mx1, __shfl_xor_sync(0xffffffffu, mx1, 1));
        mx1 = fmaxf(mx1, __shfl_xor_sync(0xffffffffu, mx1, 2));

        const float mn0 = fmaxf(mrow[0], mx0);
        const float mn1 = fmaxf(mrow[1], mx1);
        const float al0 = __expf(mrow[0] - mn0);
        const float al1 = __expf(mrow[1] - mn1);
        mrow[0] = mn0; mrow[1] = mn1;

        float sum0 = 0.f, sum1 = 0.f;
#pragma unroll
        for (int nj = 0; nj < 8; nj++) {
            s[nj][0] = __expf(s[nj][0] - mn0); sum0 += s[nj][0];
            s[nj][1] = __expf(s[nj][1] - mn0); sum0 += s[nj][1];
            s[nj][2] = __expf(s[nj][2] - mn1); sum1 += s[nj][2];
            s[nj][3] = __expf(s[nj][3] - mn1); sum1 += s[nj][3];
        }
        sum0 += __shfl_xor_sync(0xffffffffu, sum0, 1);
        sum0 += __shfl_xor_sync(0xffffffffu, sum0, 2);
        sum1 += __shfl_xor_sync(0xffffffffu, sum1, 1);
        sum1 += __shfl_xor_sync(0xffffffffu, sum1, 2);
        lrow[0] = lrow[0] * al0 + sum0;
        lrow[1] = lrow[1] * al1 + sum1;

#pragma unroll
        for (int nj = 0; nj < 8; nj++) {
            o[nj][0] *= al0; o[nj][1] *= al0;
            o[nj][2] *= al1; o[nj][3] *= al1;
        }

        // ---- P -> smem (half), warp-private rows ----
        {
            __half* p0 = &Ss[(warp * 16 + r0) * AS + cb];
            __half* p1 = &Ss[(warp * 16 + r0 + 8) * AS + cb];
#pragma unroll
            for (int nj = 0; nj < 8; nj++) {
                *(__half2*)(p0 + nj * 8) = __floats2half2_rn(s[nj][0], s[nj][1]);
                *(__half2*)(p1 + nj * 8) = __floats2half2_rn(s[nj][2], s[nj][3]);
            }
        }
        __syncwarp();

        // ---- O += P @ V ----
#pragma unroll
        for (int kc = 0; kc < 4; kc++) {
            const uint32_t ko = (uint32_t)(kc * 32);
            uint32_t a[4], b[4][4];
            ldsm4(a, poff + ko);
#pragma unroll
            for (int np = 0; np < 4; np++) ldsm4(b[np], voff[np] + ko);
#pragma unroll
            for (int nj = 0; nj < 8; nj++) {
                const int np = nj >> 1, hb = (nj & 1) << 1;
                mma16(o[nj], a, b[np][hb], b[np][hb + 1]);
            }
        }
    }

    // ---- normalize + write (half) ----
    {
        const float inv0 = 1.f / lrow[0];
        const float inv1 = 1.f / lrow[1];
        const size_t row0 = (size_t)(seg * LL + q0 + warp * 16 + r0);
#pragma unroll
        for (int nj = 0; nj < 8; nj++) {
            const int col = h * DD + nj * 8 + cb;
            *(__half2*)&g_oh[row0 * EE + col] =
                __floats2half2_rn(o[nj][0] * inv0, o[nj][1] * inv0);
            *(__half2*)&g_oh[(row0 + 8) * EE + col] =
                __floats2half2_rn(o[nj][2] * inv1, o[nj][3] * inv1);
        }
    }
}

// ---------------------------------------------------------------------------

extern "C" void kernel_launch(void* const* d_in, const int* in_sizes, int n_in,
                              void* d_out, int out_size)
{
    const float* hs   = (const float*)d_in[0];
    const float* mask = (const float*)d_in[2];
    const float* wq   = (const float*)d_in[3];
    const float* bq   = (const float*)d_in[4];
    const float* wk   = (const float*)d_in[5];
    const float* wv   = (const float*)d_in[6];
    const float* bv   = (const float*)d_in[7];
    const float* wo   = (const float*)d_in[8];
    const float* bo   = (const float*)d_in[9];
    float* out = (float*)d_out;

    __half *hh, *wh, *qh, *kh, *vth, *oh;
    cudaGetSymbolAddress((void**)&hh,  g_hh);
    cudaGetSymbolAddress((void**)&wh,  g_wh);
    cudaGetSymbolAddress((void**)&qh,  g_qh);
    cudaGetSymbolAddress((void**)&kh,  g_kh);
    cudaGetSymbolAddress((void**)&vth, g_vth);
    cudaGetSymbolAddress((void**)&oh,  g_oh);

    const int gsmem = NSTAGE * STGB;              // 81920
    cudaFuncSetAttribute(gemm_h, cudaFuncAttributeMaxDynamicSharedMemorySize, gsmem);
    const int asmem = 4 * TILEH;                  // 36864
    cudaFuncSetAttribute(attn_h, cudaFuncAttributeMaxDynamicSharedMemorySize, asmem);

    const dim3 gg(EE / 128, TT / 128);
    const int nAct4 = TT * EE / 4;
    const int nW4   = EE * EE / 4;

    // conversions
    f2h_kernel<<<nAct4 / 256, 256>>>(hs, hh, nAct4);
    f2h_kernel<<<nW4 / 256, 256>>>(wq, wh + 0 * (size_t)EE * EE, nW4);
    f2h_kernel<<<nW4 / 256, 256>>>(wk, wh + 1 * (size_t)EE * EE, nW4);
    f2h_kernel<<<nW4 / 256, 256>>>(wv, wh + 2 * (size_t)EE * EE, nW4);
    f2h_kernel<<<nW4 / 256, 256>>>(wo, wh + 3 * (size_t)EE * EE, nW4);

    // projections
    gemm_h<<<gg, 256, gsmem>>>(hh, wh + 0 * (size_t)EE * EE, bq,      qh,  nullptr, 0);
    gemm_h<<<gg, 256, gsmem>>>(hh, wh + 1 * (size_t)EE * EE, nullptr, kh,  nullptr, 0);
    gemm_h<<<gg, 256, gsmem>>>(hh, wh + 2 * (size_t)EE * EE, bv,      vth, nullptr, 1);

    // attention
    attn_h<<<dim3(LL / 64, HH, NSEG), 128, asmem>>>(mask);

    // output projection (float out + bias)
    gemm_h<<<gg, 256, gsmem>>>(oh, wh + 3 * (size_t)EE * EE, bo, nullptr, out, 2);
}

// round 8
// speedup vs baseline: 5.3948x; 1.1592x over previous
#include <cuda_runtime.h>
#include <cuda_fp16.h>
#include <math.h>
#include <stdint.h>

#define TT   8192
#define EE   1024
#define HH   16
#define DD   64
#define NSEG 8
#define LL   1024

// Scratch (device globals — no allocation allowed in kernel_launch)
__device__ __half g_hh [TT * EE];       // hs in half
__device__ __half g_wh [4 * EE * EE];   // 4 weights in half
__device__ __half g_qh [TT * EE];       // Q projection (half)
__device__ __half g_kh [TT * EE];       // K projection (half)
__device__ __half g_vth[EE * TT];       // V projection, transposed [e][token]
__device__ __half g_oh [TT * EE];       // attention output (half)

// ---------------------------------------------------------------------------
// helpers
// ---------------------------------------------------------------------------
__device__ __forceinline__ void ldsm4(uint32_t* r, uint32_t addr) {
    asm volatile("ldmatrix.sync.aligned.m8n8.x4.shared.b16 {%0,%1,%2,%3}, [%4];"
                 : "=r"(r[0]), "=r"(r[1]), "=r"(r[2]), "=r"(r[3]) : "r"(addr));
}
__device__ __forceinline__ void mma16(float* c, const uint32_t* a, uint32_t b0, uint32_t b1) {
    asm volatile("mma.sync.aligned.m16n8k16.row.col.f32.f16.f16.f32 "
                 "{%0,%1,%2,%3}, {%4,%5,%6,%7}, {%8,%9}, {%0,%1,%2,%3};"
                 : "+f"(c[0]), "+f"(c[1]), "+f"(c[2]), "+f"(c[3])
                 : "r"(a[0]), "r"(a[1]), "r"(a[2]), "r"(a[3]), "r"(b0), "r"(b1));
}
__device__ __forceinline__ void cp_async16(uint32_t dst, const void* src) {
    asm volatile("cp.async.cg.shared.global [%0], [%1], 16;\n" :: "r"(dst), "l"(src));
}
__device__ __forceinline__ void cp_commit() { asm volatile("cp.async.commit_group;\n"); }
template <int N> __device__ __forceinline__ void cp_wait() {
    asm volatile("cp.async.wait_group %0;\n" :: "n"(N));
}

// ---------------------------------------------------------------------------
// fused float -> half conversion: hs (8M floats) + 4 weights (1M each)
// ---------------------------------------------------------------------------
__global__ void f2h_all(const float* __restrict__ hs,
                        const float* __restrict__ w0, const float* __restrict__ w1,
                        const float* __restrict__ w2, const float* __restrict__ w3,
                        __half* __restrict__ hh, __half* __restrict__ wh)
{
    const int nAct4 = TT * EE / 4;
    const int nW4   = EE * EE / 4;
    int i = blockIdx.x * blockDim.x + threadIdx.x;

    const float* src; __half* dst; int j;
    if (i < nAct4) { src = hs; dst = hh; j = i; }
    else {
        int t = i - nAct4;
        int w = t / nW4;
        j = t - w * nW4;
        src = (w == 0) ? w0 : (w == 1) ? w1 : (w == 2) ? w2 : w3;
        dst = wh + (size_t)w * EE * EE;
    }
    float4 v = ((const float4*)src)[j];
    __half2* o = (__half2*)dst;
    o[2 * j]     = __floats2half2_rn(v.x, v.y);
    o[2 * j + 1] = __floats2half2_rn(v.z, v.w);
}

// ---------------------------------------------------------------------------
// FP16 mma.sync GEMM: C[M,N] = A[M,K] @ B[N,K]^T (+bias).
// 128x128 tile, BK=32 halfs, 4-stage cp.async, 8 warps, warp 64x32.
// QKV-fused variant: grid.z picks weight/bias/output. mode derived from z.
// ---------------------------------------------------------------------------
#define GH      40
#define ABY     (128 * GH * 2)
#define STGB    (2 * ABY)
#define NSTAGE  4
#define NSLAB   (EE / 32)

struct GemmOut { __half* q; __half* k; __half* vt; };

__device__ __forceinline__ void gemm_core(
    const __half* __restrict__ A, const __half* __restrict__ B, float c[4][4][4],
    uint32_t smemBase, int tid, int rowBase, int colBase,
    const uint32_t* aoff, const uint32_t* boff)
{
    const int lr = tid >> 1;
    const int lc = (tid & 1) * 8;
    const __half* Aptr = A + (size_t)(rowBase + lr) * EE + lc;
    const __half* Bptr = B + (size_t)(colBase + lr) * EE + lc;
    const uint32_t sA = smemBase + (uint32_t)((lr * GH + lc) * 2);
    const uint32_t sB = sA + ABY;

#pragma unroll
    for (int st = 0; st < NSTAGE - 1; st++) {
        const uint32_t bb = st * STGB;
        const int k0 = st * 32;
        cp_async16(sA + bb,      Aptr + k0);
        cp_async16(sA + bb + 32, Aptr + k0 + 16);
        cp_async16(sB + bb,      Bptr + k0);
        cp_async16(sB + bb + 32, Bptr + k0 + 16);
        cp_commit();
    }

    for (int s = 0; s < NSLAB; s++) {
        cp_wait<2>();
        __syncthreads();

        const uint32_t bb = (uint32_t)(s & 3) * STGB;
#pragma unroll
        for (int kk = 0; kk < 2; kk++) {
            const uint32_t ko = (uint32_t)(kk * 32);
            uint32_t a[4][4], b[2][4];
#pragma unroll
            for (int mi = 0; mi < 4; mi++)
                ldsm4(a[mi], smemBase + bb + aoff[mi] + ko);
#pragma unroll
            for (int np = 0; np < 2; np++)
                ldsm4(b[np], smemBase + bb + boff[np] + ko);
#pragma unroll
            for (int mi = 0; mi < 4; mi++)
#pragma unroll
                for (int nj = 0; nj < 4; nj++) {
                    const int np = nj >> 1, hb = (nj & 1) << 1;
                    mma16(c[mi][nj], a[mi], b[np][hb], b[np][hb + 1]);
                }
        }
        __syncthreads();

        const int sn = s + NSTAGE - 1;
        if (sn < NSLAB) {
            const uint32_t nb = (uint32_t)(sn & 3) * STGB;
            const int k0 = sn * 32;
            cp_async16(sA + nb,      Aptr + k0);
            cp_async16(sA + nb + 32, Aptr + k0 + 16);
            cp_async16(sB + nb,      Bptr + k0);
            cp_async16(sB + nb + 32, Bptr + k0 + 16);
        }
        cp_commit();
    }
}

__device__ __forceinline__ void frag_offsets(int warp, int lane, uint32_t* aoff, uint32_t* boff)
{
    const int mW = (warp >> 2) * 64;
    const int nW = (warp & 3) * 32;
#pragma unroll
    for (int mi = 0; mi < 4; mi++)
        aoff[mi] = (uint32_t)(((mW + mi * 16 + (lane & 15)) * GH + ((lane >> 4) << 3)) << 1);
#pragma unroll
    for (int np = 0; np < 2; np++)
        boff[np] = (uint32_t)(((nW + np * 16 + (lane & 7) + ((lane >> 4) << 3)) * GH
                               + (((lane >> 3) & 1) << 3)) << 1) + ABY;
}

// QKV fused projection GEMM: grid (8, 64, 3)
__global__ __launch_bounds__(256, 2)
void gemm_qkv(const __half* __restrict__ A, const __half* __restrict__ W,
              const float* __restrict__ bq, const float* __restrict__ bv,
              __half* __restrict__ Q, __half* __restrict__ K, __half* __restrict__ Vt)
{
    extern __shared__ char smc[];
    const uint32_t smemBase = (uint32_t)__cvta_generic_to_shared(smc);

    const int tid  = threadIdx.x;
    const int warp = tid >> 5;
    const int lane = tid & 31;
    const int z    = blockIdx.z;
    const int rowBase = blockIdx.y * 128;
    const int colBase = blockIdx.x * 128;

    uint32_t aoff[4], boff[2];
    frag_offsets(warp, lane, aoff, boff);

    float c[4][4][4];
#pragma unroll
    for (int mi = 0; mi < 4; mi++)
#pragma unroll
        for (int nj = 0; nj < 4; nj++)
#pragma unroll
            for (int r = 0; r < 4; r++) c[mi][nj][r] = 0.f;

    const __half* B = W + (size_t)z * EE * EE;
    gemm_core(A, B, c, smemBase, tid, rowBase, colBase, aoff, boff);

    const float* bias = (z == 0) ? bq : (z == 2) ? bv : nullptr;
    const int nW = (warp & 3) * 32;
    const int mW = (warp >> 2) * 64;

#pragma unroll
    for (int nj = 0; nj < 4; nj++) {
        const int col = colBase + nW + nj * 8 + (lane & 3) * 2;
        const float b0 = bias ? bias[col]     : 0.f;
        const float b1 = bias ? bias[col + 1] : 0.f;
#pragma unroll
        for (int mi = 0; mi < 4; mi++) {
            const int row = rowBase + mW + mi * 16 + (lane >> 2);
            const float v00 = c[mi][nj][0] + b0, v01 = c[mi][nj][1] + b1;
            const float v10 = c[mi][nj][2] + b0, v11 = c[mi][nj][3] + b1;
            if (z == 0) {
                *(__half2*)&Q[(size_t)row * EE + col]       = __floats2half2_rn(v00, v01);
                *(__half2*)&Q[(size_t)(row + 8) * EE + col] = __floats2half2_rn(v10, v11);
            } else if (z == 1) {
                *(__half2*)&K[(size_t)row * EE + col]       = __floats2half2_rn(v00, v01);
                *(__half2*)&K[(size_t)(row + 8) * EE + col] = __floats2half2_rn(v10, v11);
            } else {
                Vt[(size_t)col * TT + row]           = __float2half_rn(v00);
                Vt[(size_t)(col + 1) * TT + row]     = __float2half_rn(v01);
                Vt[(size_t)col * TT + row + 8]       = __float2half_rn(v10);
                Vt[(size_t)(col + 1) * TT + row + 8] = __float2half_rn(v11);
            }
        }
    }
}

// Output projection GEMM: C float + bias
__global__ __launch_bounds__(256, 2)
void gemm_out(const __half* __restrict__ A, const __half* __restrict__ B,
              const float* __restrict__ bias, float* __restrict__ C)
{
    extern __shared__ char smc[];
    const uint32_t smemBase = (uint32_t)__cvta_generic_to_shared(smc);

    const int tid  = threadIdx.x;
    const int warp = tid >> 5;
    const int lane = tid & 31;
    const int rowBase = blockIdx.y * 128;
    const int colBase = blockIdx.x * 128;

    uint32_t aoff[4], boff[2];
    frag_offsets(warp, lane, aoff, boff);

    float c[4][4][4];
#pragma unroll
    for (int mi = 0; mi < 4; mi++)
#pragma unroll
        for (int nj = 0; nj < 4; nj++)
#pragma unroll
            for (int r = 0; r < 4; r++) c[mi][nj][r] = 0.f;

    gemm_core(A, B, c, smemBase, tid, rowBase, colBase, aoff, boff);

    const int nW = (warp & 3) * 32;
    const int mW = (warp >> 2) * 64;
#pragma unroll
    for (int nj = 0; nj < 4; nj++) {
        const int col = colBase + nW + nj * 8 + (lane & 3) * 2;
        const float b0 = bias[col], b1 = bias[col + 1];
#pragma unroll
        for (int mi = 0; mi < 4; mi++) {
            const int row = rowBase + mW + mi * 16 + (lane >> 2);
            *(float2*)&C[(size_t)row * EE + col] =
                make_float2(c[mi][nj][0] + b0, c[mi][nj][1] + b1);
            *(float2*)&C[(size_t)(row + 8) * EE + col] =
                make_float2(c[mi][nj][2] + b0, c[mi][nj][3] + b1);
        }
    }
}

// ---------------------------------------------------------------------------
// FP16 tensor-core flash attention, 128 q-rows/CTA, 8 warps,
// double-buffered cp.async K/V tiles.
// grid (LL/128, HH, NSEG) = (8,16,8), 256 threads.
// ---------------------------------------------------------------------------
#define AS      72                       // tile row stride (halfs)
#define QBYTES  (128 * AS * 2)           // 18432
#define KVBYTES (64 * AS * 2)            // 9216
#define KOFFB(b) (QBYTES + (b) * 2 * KVBYTES)
#define VOFFB(b) (KOFFB(b) + KVBYTES)
#define SOFFB   (QBYTES + 4 * KVBYTES)   // Ss after 2 stage pairs

__global__ __launch_bounds__(256, 2)
void attn_h(const float* __restrict__ mask)
{
    extern __shared__ char smc[];
    __half* Qs = (__half*)smc;
    __half* Ss = (__half*)(smc + SOFFB);
    const uint32_t smemBase = (uint32_t)__cvta_generic_to_shared(smc);

    const int seg = blockIdx.z;
    const int h   = blockIdx.y;
    const int q0  = blockIdx.x * 128;
    const int tid = threadIdx.x;
    const int warp = tid >> 5;
    const int lane = tid & 31;
    const int r0 = lane >> 2;
    const int cb = (lane & 3) * 2;

    // Q tile load (128 rows x 64 halfs)
    for (int i = tid; i < 128 * 8; i += 256) {
        const int r = i >> 3, c8 = (i & 7) * 8;
        *(uint4*)&Qs[r * AS + c8] =
            *(const uint4*)&g_qh[(size_t)(seg * LL + q0 + r) * EE + h * DD + c8];
    }

    // fragment offsets
    const uint32_t qoff = smemBase + (uint32_t)(((warp * 16 + (lane & 15)) * AS
                                                 + ((lane >> 4) << 3)) << 1);
    const uint32_t poff = qoff + (uint32_t)SOFFB;
    uint32_t kvoff[4];
#pragma unroll
    for (int np = 0; np < 4; np++)
        kvoff[np] = (uint32_t)(((np * 16 + (lane & 7) + ((lane >> 4) << 3)) * AS
                                + (((lane >> 3) & 1) << 3)) << 1);

    // K/V loader mapping: 2 chunks each of K and V per thread
    const int ch0 = tid * 2;             // chunk ids ch0, ch0+1 in [0,512)
    const __half* kbase = &g_kh[(size_t)(seg * LL) * EE + h * DD];
    const __half* vbase = &g_vth[(size_t)(h * DD) * TT + seg * LL];

    float o[8][4];
#pragma unroll
    for (int nj = 0; nj < 8; nj++)
#pragma unroll
        for (int r = 0; r < 4; r++) o[nj][r] = 0.f;
    float mrow[2] = {-INFINITY, -INFINITY};
    float lrow[2] = {0.f, 0.f};

    // prologue: tile 0 -> buffer 0
    {
#pragma unroll
        for (int u = 0; u < 2; u++) {
            const int ch = ch0 + u;
            const int r = ch >> 3, c8 = (ch & 7) * 8;
            cp_async16(smemBase + KOFFB(0) + (uint32_t)((r * AS + c8) << 1),
                       kbase + (size_t)r * EE + c8);
            cp_async16(smemBase + VOFFB(0) + (uint32_t)((r * AS + c8) << 1),
                       vbase + (size_t)r * TT + c8);
        }
        cp_commit();
    }

    for (int kt = 0; kt < 16; kt++) {
        const int k0 = kt * 64;
        // prefetch tile kt+1 into buffer (kt+1)&1
        if (kt + 1 < 16) {
            const int kn = (kt + 1) * 64;
            const uint32_t kb = smemBase + KOFFB((kt + 1) & 1);
            const uint32_t vb = smemBase + VOFFB((kt + 1) & 1);
#pragma unroll
            for (int u = 0; u < 2; u++) {
                const int ch = ch0 + u;
                const int r = ch >> 3, c8 = (ch & 7) * 8;
                cp_async16(kb + (uint32_t)((r * AS + c8) << 1),
                           kbase + (size_t)(kn + r) * EE + c8);
                cp_async16(vb + (uint32_t)((r * AS + c8) << 1),
                           vbase + (size_t)r * TT + kn + c8);
            }
        }
        cp_commit();
        cp_wait<1>();        // tile kt resident
        __syncthreads();

        const uint32_t kbuf = smemBase + KOFFB(kt & 1);
        const uint32_t vbuf = smemBase + VOFFB(kt & 1);

        // ---- S = Q @ K^T ----
        float s[8][4];
#pragma unroll
        for (int nj = 0; nj < 8; nj++)
#pragma unroll
            for (int r = 0; r < 4; r++) s[nj][r] = 0.f;

#pragma unroll
        for (int kd = 0; kd < 4; kd++) {
            const uint32_t ko = (uint32_t)(kd * 32);
            uint32_t a[4], b[4][4];
            ldsm4(a, qoff + ko);
#pragma unroll
            for (int np = 0; np < 4; np++) ldsm4(b[np], kbuf + kvoff[np] + ko);
#pragma unroll
            for (int nj = 0; nj < 8; nj++) {
                const int np = nj >> 1, hb = (nj & 1) << 1;
                mma16(s[nj], a, b[np][hb], b[np][hb + 1]);
            }
        }

        // ---- scale + mask ----
        {
            const size_t mbase = (size_t)(seg * LL + q0 + warp * 16 + r0) * TT
                               + (size_t)(seg * LL + k0) + cb;
#pragma unroll
            for (int nj = 0; nj < 8; nj++) {
                float2 m0 = *(const float2*)&mask[mbase + nj * 8];
                float2 m1 = *(const float2*)&mask[mbase + nj * 8 + (size_t)8 * TT];
                s[nj][0] = s[nj][0] * 0.125f + m0.x;
                s[nj][1] = s[nj][1] * 0.125f + m0.y;
                s[nj][2] = s[nj][2] * 0.125f + m1.x;
                s[nj][3] = s[nj][3] * 0.125f + m1.y;
            }
        }

        // ---- online softmax ----
        float mx0 = s[0][0], mx1 = s[0][2];
#pragma unroll
        for (int nj = 0; nj < 8; nj++) {
            mx0 = fmaxf(mx0, fmaxf(s[nj][0], s[nj][1]));
            mx1 = fmaxf(mx1, fmaxf(s[nj][2], s[nj][3]));
        }
        mx0 = fmaxf(mx0, __shfl_xor_sync(0xffffffffu, mx0, 1));
        mx0 = fmaxf(mx0, __shfl_xor_sync(0xffffffffu, mx0, 2));
        mx1 = fmaxf(mx1, __shfl_xor_sync(0xffffffffu, mx1, 1));
        mx1 = fmaxf(mx1, __shfl_xor_sync(0xffffffffu, mx1, 2));

        const float mn0 = fmaxf(mrow[0], mx0);
        const float mn1 = fmaxf(mrow[1], mx1);
        const float al0 = __expf(mrow[0] - mn0);
        const float al1 = __expf(mrow[1] - mn1);
        mrow[0] = mn0; mrow[1] = mn1;

        float sum0 = 0.f, sum1 = 0.f;
#pragma unroll
        for (int nj = 0; nj < 8; nj++) {
            s[nj][0] = __expf(s[nj][0] - mn0); sum0 += s[nj][0];
            s[nj][1] = __expf(s[nj][1] - mn0); sum0 += s[nj][1];
            s[nj][2] = __expf(s[nj][2] - mn1); sum1 += s[nj][2];
            s[nj][3] = __expf(s[nj][3] - mn1); sum1 += s[nj][3];
        }
        sum0 += __shfl_xor_sync(0xffffffffu, sum0, 1);
        sum0 += __shfl_xor_sync(0xffffffffu, sum0, 2);
        sum1 += __shfl_xor_sync(0xffffffffu, sum1, 1);
        sum1 += __shfl_xor_sync(0xffffffffu, sum1, 2);
        lrow[0] = lrow[0] * al0 + sum0;
        lrow[1] = lrow[1] * al1 + sum1;

#pragma unroll
        for (int nj = 0; nj < 8; nj++) {
            o[nj][0] *= al0; o[nj][1] *= al0;
            o[nj][2] *= al1; o[nj][3] *= al1;
        }

        // ---- P -> smem (half), warp-private rows ----
        {
            __half* p0 = &Ss[(warp * 16 + r0) * AS + cb];
            __half* p1 = &Ss[(warp * 16 + r0 + 8) * AS + cb];
#pragma unroll
            for (int nj = 0; nj < 8; nj++) {
                *(__half2*)(p0 + nj * 8) = __floats2half2_rn(s[nj][0], s[nj][1]);
                *(__half2*)(p1 + nj * 8) = __floats2half2_rn(s[nj][2], s[nj][3]);
            }
        }
        __syncwarp();

        // ---- O += P @ V ----
#pragma unroll
        for (int kc = 0; kc < 4; kc++) {
            const uint32_t ko = (uint32_t)(kc * 32);
            uint32_t a[4], b[4][4];
            ldsm4(a, poff + ko);
#pragma unroll
            for (int np = 0; np < 4; np++) ldsm4(b[np], vbuf + kvoff[np] + ko);
#pragma unroll
            for (int nj = 0; nj < 8; nj++) {
                const int np = nj >> 1, hb = (nj & 1) << 1;
                mma16(o[nj], a, b[np][hb], b[np][hb + 1]);
            }
        }
        __syncthreads();   // all warps done with buffer (kt&1) before refill at kt+2
    }

    // ---- normalize + write (half) ----
    {
        const float inv0 = 1.f / lrow[0];
        const float inv1 = 1.f / lrow[1];
        const size_t row0 = (size_t)(seg * LL + q0 + warp * 16 + r0);
#pragma unroll
        for (int nj = 0; nj < 8; nj++) {
            const int col = h * DD + nj * 8 + cb;
            *(__half2*)&g_oh[row0 * EE + col] =
                __floats2half2_rn(o[nj][0] * inv0, o[nj][1] * inv0);
            *(__half2*)&g_oh[(row0 + 8) * EE + col] =
                __floats2half2_rn(o[nj][2] * inv1, o[nj][3] * inv1);
        }
    }
}

// ---------------------------------------------------------------------------

extern "C" void kernel_launch(void* const* d_in, const int* in_sizes, int n_in,
                              void* d_out, int out_size)
{
    const float* hs   = (const float*)d_in[0];
    const float* mask = (const float*)d_in[2];
    const float* wq   = (const float*)d_in[3];
    const float* bq   = (const float*)d_in[4];
    const float* wk   = (const float*)d_in[5];
    const float* wv   = (const float*)d_in[6];
    const float* bv   = (const float*)d_in[7];
    const float* wo   = (const float*)d_in[8];
    const float* bo   = (const float*)d_in[9];
    float* out = (float*)d_out;

    __half *hh, *wh, *qh, *kh, *vth, *oh;
    cudaGetSymbolAddress((void**)&hh,  g_hh);
    cudaGetSymbolAddress((void**)&wh,  g_wh);
    cudaGetSymbolAddress((void**)&qh,  g_qh);
    cudaGetSymbolAddress((void**)&kh,  g_kh);
    cudaGetSymbolAddress((void**)&vth, g_vth);
    cudaGetSymbolAddress((void**)&oh,  g_oh);

    const int gsmem = NSTAGE * STGB;              // 81920
    cudaFuncSetAttribute(gemm_qkv, cudaFuncAttributeMaxDynamicSharedMemorySize, gsmem);
    cudaFuncSetAttribute(gemm_out, cudaFuncAttributeMaxDynamicSharedMemorySize, gsmem);
    const int asmem = SOFFB + QBYTES;             // 73728 + 18432? (S = 128 rows)
    cudaFuncSetAttribute(attn_h, cudaFuncAttributeMaxDynamicSharedMemorySize, asmem);

    // conversions (single launch)
    const int nConv = (TT * EE + 4 * EE * EE) / 4;
    f2h_all<<<nConv / 256, 256>>>(hs, wq, wk, wv, wo, hh, wh);

    // fused QKV projections
    gemm_qkv<<<dim3(EE / 128, TT / 128, 3), 256, gsmem>>>(hh, wh, bq, bv, qh, kh, vth);

    // attention
    attn_h<<<dim3(LL / 128, HH, NSEG), 256, asmem>>>(mask);

    // output projection
    gemm_out<<<dim3(EE / 128, TT / 128), 256, gsmem>>>(oh, wh + 3 * (size_t)EE * EE, bo, out);
}

// round 9
// speedup vs baseline: 5.5730x; 1.0330x over previous
#include <cuda_runtime.h>
#include <cuda_fp16.h>
#include <math.h>
#include <stdint.h>

#define TT   8192
#define EE   1024
#define HH   16
#define DD   64
#define NSEG 8
#define LL   1024

// Scratch (device globals — no allocation allowed in kernel_launch)
__device__ __half g_hh [TT * EE];       // hs in half
__device__ __half g_wh [4 * EE * EE];   // 4 weights in half
__device__ __half g_qh [TT * EE];       // Q projection (half)
__device__ __half g_kh [TT * EE];       // K projection (half)
__device__ __half g_vth[EE * TT];       // V projection, transposed [e][token]
__device__ __half g_oh [TT * EE];       // attention output (half)

// ---------------------------------------------------------------------------
// helpers
// ---------------------------------------------------------------------------
__device__ __forceinline__ void ldsm4(uint32_t* r, uint32_t addr) {
    asm volatile("ldmatrix.sync.aligned.m8n8.x4.shared.b16 {%0,%1,%2,%3}, [%4];"
                 : "=r"(r[0]), "=r"(r[1]), "=r"(r[2]), "=r"(r[3]) : "r"(addr));
}
__device__ __forceinline__ void mma16(float* c, const uint32_t* a, uint32_t b0, uint32_t b1) {
    asm volatile("mma.sync.aligned.m16n8k16.row.col.f32.f16.f16.f32 "
                 "{%0,%1,%2,%3}, {%4,%5,%6,%7}, {%8,%9}, {%0,%1,%2,%3};"
                 : "+f"(c[0]), "+f"(c[1]), "+f"(c[2]), "+f"(c[3])
                 : "r"(a[0]), "r"(a[1]), "r"(a[2]), "r"(a[3]), "r"(b0), "r"(b1));
}
__device__ __forceinline__ void cp_async16(uint32_t dst, const void* src) {
    asm volatile("cp.async.cg.shared.global [%0], [%1], 16;\n" :: "r"(dst), "l"(src));
}
__device__ __forceinline__ void cp_commit() { asm volatile("cp.async.commit_group;\n"); }
template <int N> __device__ __forceinline__ void cp_wait() {
    asm volatile("cp.async.wait_group %0;\n" :: "n"(N));
}

// ---------------------------------------------------------------------------
// fused float -> half conversion
// ---------------------------------------------------------------------------
__global__ void f2h_all(const float* __restrict__ hs,
                        const float* __restrict__ w0, const float* __restrict__ w1,
                        const float* __restrict__ w2, const float* __restrict__ w3,
                        __half* __restrict__ hh, __half* __restrict__ wh)
{
    const int nAct4 = TT * EE / 4;
    const int nW4   = EE * EE / 4;
    int i = blockIdx.x * blockDim.x + threadIdx.x;

    const float* src; __half* dst; int j;
    if (i < nAct4) { src = hs; dst = hh; j = i; }
    else {
        int t = i - nAct4;
        int w = t / nW4;
        j = t - w * nW4;
        src = (w == 0) ? w0 : (w == 1) ? w1 : (w == 2) ? w2 : w3;
        dst = wh + (size_t)w * EE * EE;
    }
    float4 v = ((const float4*)src)[j];
    __half2* o = (__half2*)dst;
    o[2 * j]     = __floats2half2_rn(v.x, v.y);
    o[2 * j + 1] = __floats2half2_rn(v.z, v.w);
}

// ---------------------------------------------------------------------------
// FP16 mma.sync GEMM core: 128x128 tile, BK=32, 5-stage cp.async,
// ONE barrier per slab. 8 warps (2x4), warp 64x32.
// ---------------------------------------------------------------------------
#define GH      40
#define ABY     (128 * GH * 2)            // 10240
#define STGB    (2 * ABY)                 // 20480
#define NSTAGE  5
#define NSLAB   (EE / 32)                 // 32

__device__ __forceinline__ void frag_offsets(int warp, int lane, uint32_t* aoff, uint32_t* boff)
{
    const int mW = (warp >> 2) * 64;
    const int nW = (warp & 3) * 32;
#pragma unroll
    for (int mi = 0; mi < 4; mi++)
        aoff[mi] = (uint32_t)(((mW + mi * 16 + (lane & 15)) * GH + ((lane >> 4) << 3)) << 1);
#pragma unroll
    for (int np = 0; np < 2; np++)
        boff[np] = (uint32_t)(((nW + np * 16 + (lane & 7) + ((lane >> 4) << 3)) * GH
                               + (((lane >> 3) & 1) << 3)) << 1) + ABY;
}

__device__ __forceinline__ void gemm_core(
    const __half* __restrict__ A, const __half* __restrict__ B, float c[4][4][4],
    uint32_t smemBase, int tid, int rowBase, int colBase,
    const uint32_t* aoff, const uint32_t* boff)
{
    const int lr = tid >> 1;
    const int lc = (tid & 1) * 8;
    const __half* Aptr = A + (size_t)(rowBase + lr) * EE + lc;
    const __half* Bptr = B + (size_t)(colBase + lr) * EE + lc;
    const uint32_t sA = smemBase + (uint32_t)((lr * GH + lc) * 2);
    const uint32_t sB = sA + ABY;

    // prologue: stages 0..3
#pragma unroll
    for (int st = 0; st < NSTAGE - 1; st++) {
        const uint32_t bb = st * STGB;
        const int k0 = st * 32;
        cp_async16(sA + bb,      Aptr + k0);
        cp_async16(sA + bb + 32, Aptr + k0 + 16);
        cp_async16(sB + bb,      Bptr + k0);
        cp_async16(sB + bb + 32, Bptr + k0 + 16);
        cp_commit();
    }

    for (int s = 0; s < NSLAB; s++) {
        cp_wait<NSTAGE - 2>();     // slab s resident
        __syncthreads();           // all warps done reading buffer (s-1)%NSTAGE

        // refill buffer (s + NSTAGE-1) % NSTAGE == (s-1) % NSTAGE — safe post-barrier
        const int sn = s + NSTAGE - 1;
        if (sn < NSLAB) {
            const uint32_t nb = (uint32_t)(sn % NSTAGE) * STGB;
            const int k0 = sn * 32;
            cp_async16(sA + nb,      Aptr + k0);
            cp_async16(sA + nb + 32, Aptr + k0 + 16);
            cp_async16(sB + nb,      Bptr + k0);
            cp_async16(sB + nb + 32, Bptr + k0 + 16);
        }
        cp_commit();

        const uint32_t bb = (uint32_t)(s % NSTAGE) * STGB;
#pragma unroll
        for (int kk = 0; kk < 2; kk++) {
            const uint32_t ko = (uint32_t)(kk * 32);
            uint32_t a[4][4], b[2][4];
#pragma unroll
            for (int mi = 0; mi < 4; mi++)
                ldsm4(a[mi], smemBase + bb + aoff[mi] + ko);
#pragma unroll
            for (int np = 0; np < 2; np++)
                ldsm4(b[np], smemBase + bb + boff[np] + ko);
#pragma unroll
            for (int mi = 0; mi < 4; mi++)
#pragma unroll
                for (int nj = 0; nj < 4; nj++) {
                    const int np = nj >> 1, hb = (nj & 1) << 1;
                    mma16(c[mi][nj], a[mi], b[np][hb], b[np][hb + 1]);
                }
        }
    }
}

// QKV fused projection GEMM: grid (8, 64, 3)
__global__ __launch_bounds__(256, 2)
void gemm_qkv(const __half* __restrict__ A, const __half* __restrict__ W,
              const float* __restrict__ bq, const float* __restrict__ bv,
              __half* __restrict__ Q, __half* __restrict__ K, __half* __restrict__ Vt)
{
    extern __shared__ char smc[];
    const uint32_t smemBase = (uint32_t)__cvta_generic_to_shared(smc);

    const int tid  = threadIdx.x;
    const int warp = tid >> 5;
    const int lane = tid & 31;
    const int z    = blockIdx.z;
    const int rowBase = blockIdx.y * 128;
    const int colBase = blockIdx.x * 128;

    uint32_t aoff[4], boff[2];
    frag_offsets(warp, lane, aoff, boff);

    float c[4][4][4];
#pragma unroll
    for (int mi = 0; mi < 4; mi++)
#pragma unroll
        for (int nj = 0; nj < 4; nj++)
#pragma unroll
            for (int r = 0; r < 4; r++) c[mi][nj][r] = 0.f;

    gemm_core(A, W + (size_t)z * EE * EE, c, smemBase, tid, rowBase, colBase, aoff, boff);

    const float* bias = (z == 0) ? bq : (z == 2) ? bv : nullptr;
    const int nW = (warp & 3) * 32;
    const int mW = (warp >> 2) * 64;

    if (z != 2) {
        __half* Cp = (z == 0) ? Q : K;
#pragma unroll
        for (int nj = 0; nj < 4; nj++) {
            const int col = colBase + nW + nj * 8 + (lane & 3) * 2;
            const float b0 = bias ? bias[col]     : 0.f;
            const float b1 = bias ? bias[col + 1] : 0.f;
#pragma unroll
            for (int mi = 0; mi < 4; mi++) {
                const int row = rowBase + mW + mi * 16 + (lane >> 2);
                *(__half2*)&Cp[(size_t)row * EE + col] =
                    __floats2half2_rn(c[mi][nj][0] + b0, c[mi][nj][1] + b1);
                *(__half2*)&Cp[(size_t)(row + 8) * EE + col] =
                    __floats2half2_rn(c[mi][nj][2] + b0, c[mi][nj][3] + b1);
            }
        }
    } else {
        // V: transpose through smem, then coalesced stores to Vt[col][token]
        __syncthreads();                 // pipeline smem dead now
        __half* st = (__half*)smc;       // [128 cols][136]
#pragma unroll
        for (int nj = 0; nj < 4; nj++) {
            const int cl = nW + nj * 8 + (lane & 3) * 2;
            const float b0 = bias[colBase + cl];
            const float b1 = bias[colBase + cl + 1];
#pragma unroll
            for (int mi = 0; mi < 4; mi++) {
                const int rl = mW + mi * 16 + (lane >> 2);
                st[cl * 136 + rl]           = __float2half_rn(c[mi][nj][0] + b0);
                st[(cl + 1) * 136 + rl]     = __float2half_rn(c[mi][nj][1] + b1);
                st[cl * 136 + rl + 8]       = __float2half_rn(c[mi][nj][2] + b0);
                st[(cl + 1) * 136 + rl + 8] = __float2half_rn(c[mi][nj][3] + b1);
            }
        }
        __syncthreads();
        const int col = tid >> 1;
        const int ro  = (tid & 1) * 64;
        const __half* src = &st[col * 136 + ro];
        __half* dst = &Vt[(size_t)(colBase + col) * TT + rowBase + ro];
#pragma unroll
        for (int p = 0; p < 8; p++)
            *(uint4*)(dst + 8 * p) = *(const uint4*)(src + 8 * p);
    }
}

// Output projection GEMM: C float + bias
__global__ __launch_bounds__(256, 2)
void gemm_out(const __half* __restrict__ A, const __half* __restrict__ B,
              const float* __restrict__ bias, float* __restrict__ C)
{
    extern __shared__ char smc[];
    const uint32_t smemBase = (uint32_t)__cvta_generic_to_shared(smc);

    const int tid  = threadIdx.x;
    const int warp = tid >> 5;
    const int lane = tid & 31;
    const int rowBase = blockIdx.y * 128;
    const int colBase = blockIdx.x * 128;

    uint32_t aoff[4], boff[2];
    frag_offsets(warp, lane, aoff, boff);

    float c[4][4][4];
#pragma unroll
    for (int mi = 0; mi < 4; mi++)
#pragma unroll
        for (int nj = 0; nj < 4; nj++)
#pragma unroll
            for (int r = 0; r < 4; r++) c[mi][nj][r] = 0.f;

    gemm_core(A, B, c, smemBase, tid, rowBase, colBase, aoff, boff);

    const int nW = (warp & 3) * 32;
    const int mW = (warp >> 2) * 64;
#pragma unroll
    for (int nj = 0; nj < 4; nj++) {
        const int col = colBase + nW + nj * 8 + (lane & 3) * 2;
        const float b0 = bias[col], b1 = bias[col + 1];
#pragma unroll
        for (int mi = 0; mi < 4; mi++) {
            const int row = rowBase + mW + mi * 16 + (lane >> 2);
            *(float2*)&C[(size_t)row * EE + col] =
                make_float2(c[mi][nj][0] + b0, c[mi][nj][1] + b1);
            *(float2*)&C[(size_t)(row + 8) * EE + col] =
                make_float2(c[mi][nj][2] + b0, c[mi][nj][3] + b1);
        }
    }
}

// ---------------------------------------------------------------------------
// FP16 tensor-core flash attention, 128 q-rows/CTA, 8 warps,
// double-buffered cp.async K/V, ONE barrier per ktile.
// grid (LL/128, HH, NSEG) = (8,16,8), 256 threads.
// ---------------------------------------------------------------------------
#define AS      72
#define QBYTES  (128 * AS * 2)
#define KVBYTES (64 * AS * 2)
#define KOFFB(b) (QBYTES + (b) * 2 * KVBYTES)
#define VOFFB(b) (KOFFB(b) + KVBYTES)
#define SOFFB   (QBYTES + 4 * KVBYTES)

__global__ __launch_bounds__(256, 2)
void attn_h(const float* __restrict__ mask)
{
    extern __shared__ char smc[];
    __half* Qs = (__half*)smc;
    __half* Ss = (__half*)(smc + SOFFB);
    const uint32_t smemBase = (uint32_t)__cvta_generic_to_shared(smc);

    const int seg = blockIdx.z;
    const int h   = blockIdx.y;
    const int q0  = blockIdx.x * 128;
    const int tid = threadIdx.x;
    const int warp = tid >> 5;
    const int lane = tid & 31;
    const int r0 = lane >> 2;
    const int cb = (lane & 3) * 2;

    // Q tile load
    for (int i = tid; i < 128 * 8; i += 256) {
        const int r = i >> 3, c8 = (i & 7) * 8;
        *(uint4*)&Qs[r * AS + c8] =
            *(const uint4*)&g_qh[(size_t)(seg * LL + q0 + r) * EE + h * DD + c8];
    }

    const uint32_t qoff = smemBase + (uint32_t)(((warp * 16 + (lane & 15)) * AS
                                                 + ((lane >> 4) << 3)) << 1);
    const uint32_t poff = qoff + (uint32_t)SOFFB;
    uint32_t kvoff[4];
#pragma unroll
    for (int np = 0; np < 4; np++)
        kvoff[np] = (uint32_t)(((np * 16 + (lane & 7) + ((lane >> 4) << 3)) * AS
                                + (((lane >> 3) & 1) << 3)) << 1);

    const int ch0 = tid * 2;
    const __half* kbase = &g_kh[(size_t)(seg * LL) * EE + h * DD];
    const __half* vbase = &g_vth[(size_t)(h * DD) * TT + seg * LL];

    float o[8][4];
#pragma unroll
    for (int nj = 0; nj < 8; nj++)
#pragma unroll
        for (int r = 0; r < 4; r++) o[nj][r] = 0.f;
    float mrow[2] = {-INFINITY, -INFINITY};
    float lrow[2] = {0.f, 0.f};

    // prologue: tile 0 -> buffer 0
    {
#pragma unroll
        for (int u = 0; u < 2; u++) {
            const int ch = ch0 + u;
            const int r = ch >> 3, c8 = (ch & 7) * 8;
            cp_async16(smemBase + KOFFB(0) + (uint32_t)((r * AS + c8) << 1),
                       kbase + (size_t)r * EE + c8);
            cp_async16(smemBase + VOFFB(0) + (uint32_t)((r * AS + c8) << 1),
                       vbase + (size_t)r * TT + c8);
        }
        cp_commit();
    }

    for (int kt = 0; kt < 16; kt++) {
        const int k0 = kt * 64;
        cp_wait<0>();       // tile kt resident
        __syncthreads();    // everyone done reading buffer (kt&1) from iter kt-2; Qs ready at kt=0

        // prefetch tile kt+1 into buffer (kt+1)&1 — read last at iter kt-1, safe post-barrier
        if (kt + 1 < 16) {
            const int kn = (kt + 1) * 64;
            const uint32_t kb = smemBase + KOFFB((kt + 1) & 1);
            const uint32_t vb = smemBase + VOFFB((kt + 1) & 1);
#pragma unroll
            for (int u = 0; u < 2; u++) {
                const int ch = ch0 + u;
                const int r = ch >> 3, c8 = (ch & 7) * 8;
                cp_async16(kb + (uint32_t)((r * AS + c8) << 1),
                           kbase + (size_t)(kn + r) * EE + c8);
                cp_async16(vb + (uint32_t)((r * AS + c8) << 1),
                           vbase + (size_t)r * TT + kn + c8);
            }
        }
        cp_commit();

        const uint32_t kbuf = smemBase + KOFFB(kt & 1);
        const uint32_t vbuf = smemBase + VOFFB(kt & 1);

        // ---- S = Q @ K^T ----
        float s[8][4];
#pragma unroll
        for (int nj = 0; nj < 8; nj++)
#pragma unroll
            for (int r = 0; r < 4; r++) s[nj][r] = 0.f;

#pragma unroll
        for (int kd = 0; kd < 4; kd++) {
            const uint32_t ko = (uint32_t)(kd * 32);
            uint32_t a[4], b[4][4];
            ldsm4(a, qoff + ko);
#pragma unroll
            for (int np = 0; np < 4; np++) ldsm4(b[np], kbuf + kvoff[np] + ko);
#pragma unroll
            for (int nj = 0; nj < 8; nj++) {
                const int np = nj >> 1, hb = (nj & 1) << 1;
                mma16(s[nj], a, b[np][hb], b[np][hb + 1]);
            }
        }

        // ---- scale + mask ----
        {
            const size_t mbase = (size_t)(seg * LL + q0 + warp * 16 + r0) * TT
                               + (size_t)(seg * LL + k0) + cb;
#pragma unroll
            for (int nj = 0; nj < 8; nj++) {
                float2 m0 = *(const float2*)&mask[mbase + nj * 8];
                float2 m1 = *(const float2*)&mask[mbase + nj * 8 + (size_t)8 * TT];
                s[nj][0] = s[nj][0] * 0.125f + m0.x;
                s[nj][1] = s[nj][1] * 0.125f + m0.y;
                s[nj][2] = s[nj][2] * 0.125f + m1.x;
                s[nj][3] = s[nj][3] * 0.125f + m1.y;
            }
        }

        // ---- online softmax ----
        float mx0 = s[0][0], mx1 = s[0][2];
#pragma unroll
        for (int nj = 0; nj < 8; nj++) {
            mx0 = fmaxf(mx0, fmaxf(s[nj][0], s[nj][1]));
            mx1 = fmaxf(mx1, fmaxf(s[nj][2], s[nj][3]));
        }
        mx0 = fmaxf(mx0, __shfl_xor_sync(0xffffffffu, mx0, 1));
        mx0 = fmaxf(mx0, __shfl_xor_sync(0xffffffffu, mx0, 2));
        mx1 = fmaxf(mx1, __shfl_xor_sync(0xffffffffu, mx1, 1));
        mx1 = fmaxf(mx1, __shfl_xor_sync(0xffffffffu, mx1, 2));

        const float mn0 = fmaxf(mrow[0], mx0);
        const float mn1 = fmaxf(mrow[1], mx1);
        const float al0 = __expf(mrow[0] - mn0);
        const float al1 = __expf(mrow[1] - mn1);
        mrow[0] = mn0; mrow[1] = mn1;

        float sum0 = 0.f, sum1 = 0.f;
#pragma unroll
        for (int nj = 0; nj < 8; nj++) {
            s[nj][0] = __expf(s[nj][0] - mn0); sum0 += s[nj][0];
            s[nj][1] = __expf(s[nj][1] - mn0); sum0 += s[nj][1];
            s[nj][2] = __expf(s[nj][2] - mn1); sum1 += s[nj][2];
            s[nj][3] = __expf(s[nj][3] - mn1); sum1 += s[nj][3];
        }
        sum0 += __shfl_xor_sync(0xffffffffu, sum0, 1);
        sum0 += __shfl_xor_sync(0xffffffffu, sum0, 2);
        sum1 += __shfl_xor_sync(0xffffffffu, sum1, 1);
        sum1 += __shfl_xor_sync(0xffffffffu, sum1, 2);
        lrow[0] = lrow[0] * al0 + sum0;
        lrow[1] = lrow[1] * al1 + sum1;

#pragma unroll
        for (int nj = 0; nj < 8; nj++) {
            o[nj][0] *= al0; o[nj][1] *= al0;
            o[nj][2] *= al1; o[nj][3] *= al1;
        }

        // ---- P -> smem (half), warp-private rows ----
        {
            __half* p0 = &Ss[(warp * 16 + r0) * AS + cb];
            __half* p1 = &Ss[(warp * 16 + r0 + 8) * AS + cb];
#pragma unroll
            for (int nj = 0; nj < 8; nj++) {
                *(__half2*)(p0 + nj * 8) = __floats2half2_rn(s[nj][0], s[nj][1]);
                *(__half2*)(p1 + nj * 8) = __floats2half2_rn(s[nj][2], s[nj][3]);
            }
        }
        __syncwarp();

        // ---- O += P @ V ----
#pragma unroll
        for (int kc = 0; kc < 4; kc++) {
            const uint32_t ko = (uint32_t)(kc * 32);
            uint32_t a[4], b[4][4];
            ldsm4(a, poff + ko);
#pragma unroll
            for (int np = 0; np < 4; np++) ldsm4(b[np], vbuf + kvoff[np] + ko);
#pragma unroll
            for (int nj = 0; nj < 8; nj++) {
                const int np = nj >> 1, hb = (nj & 1) << 1;
                mma16(o[nj], a, b[np][hb], b[np][hb + 1]);
            }
        }
    }

    // ---- normalize + write (half) ----
    {
        const float inv0 = 1.f / lrow[0];
        const float inv1 = 1.f / lrow[1];
        const size_t row0 = (size_t)(seg * LL + q0 + warp * 16 + r0);
#pragma unroll
        for (int nj = 0; nj < 8; nj++) {
            const int col = h * DD + nj * 8 + cb;
            *(__half2*)&g_oh[row0 * EE + col] =
                __floats2half2_rn(o[nj][0] * inv0, o[nj][1] * inv0);
            *(__half2*)&g_oh[(row0 + 8) * EE + col] =
                __floats2half2_rn(o[nj][2] * inv1, o[nj][3] * inv1);
        }
    }
}

// ---------------------------------------------------------------------------

extern "C" void kernel_launch(void* const* d_in, const int* in_sizes, int n_in,
                              void* d_out, int out_size)
{
    const float* hs   = (const float*)d_in[0];
    const float* mask = (const float*)d_in[2];
    const float* wq   = (const float*)d_in[3];
    const float* bq   = (const float*)d_in[4];
    const float* wk   = (const float*)d_in[5];
    const float* wv   = (const float*)d_in[6];
    const float* bv   = (const float*)d_in[7];
    const float* wo   = (const float*)d_in[8];
    const float* bo   = (const float*)d_in[9];
    float* out = (float*)d_out;

    __half *hh, *wh, *qh, *kh, *vth, *oh;
    cudaGetSymbolAddress((void**)&hh,  g_hh);
    cudaGetSymbolAddress((void**)&wh,  g_wh);
    cudaGetSymbolAddress((void**)&qh,  g_qh);
    cudaGetSymbolAddress((void**)&kh,  g_kh);
    cudaGetSymbolAddress((void**)&vth, g_vth);
    cudaGetSymbolAddress((void**)&oh,  g_oh);

    const int gsmem = NSTAGE * STGB;              // 102400
    cudaFuncSetAttribute(gemm_qkv, cudaFuncAttributeMaxDynamicSharedMemorySize, gsmem);
    cudaFuncSetAttribute(gemm_out, cudaFuncAttributeMaxDynamicSharedMemorySize, gsmem);
    const int asmem = SOFFB + QBYTES;
    cudaFuncSetAttribute(attn_h, cudaFuncAttributeMaxDynamicSharedMemorySize, asmem);

    const int nConv = (TT * EE + 4 * EE * EE) / 4;
    f2h_all<<<nConv / 256, 256>>>(hs, wq, wk, wv, wo, hh, wh);

    gemm_qkv<<<dim3(EE / 128, TT / 128, 3), 256, gsmem>>>(hh, wh, bq, bv, qh, kh, vth);

    attn_h<<<dim3(LL / 128, HH, NSEG), 256, asmem>>>(mask);

    gemm_out<<<dim3(EE / 128, TT / 128), 256, gsmem>>>(oh, wh + 3 * (size_t)EE * EE, bo, out);
}